// round 12
// baseline (speedup 1.0000x reference)
#include <cuda_runtime.h>
#include <cuda_bf16.h>
#include <cstdint>

// ----------------------------------------------------------------------------
// Problem constants: B=4, S=2048 -> T=8192 tokens, HID=768, NH=12, HD=64,
// NC=8 candidates, FF=3072
// ----------------------------------------------------------------------------
#define T_TOK   8192
#define HID     768
#define NH      12
#define HD      64
#define NC      8
#define FF      3072
#define CAND_M  (T_TOK * NC)   // 65536
#define MASK_N  (T_TOK * NC)   // 65536

typedef __nv_bfloat16  bf16;
typedef __nv_bfloat162 bf162;

// ----------------------------------------------------------------------------
// Scratch (device globals -- no allocation allowed anywhere)
// ----------------------------------------------------------------------------
__device__ float g_Q  [(size_t)T_TOK  * HID];
__device__ float g_K  [(size_t)CAND_M * HID];
__device__ float g_V  [(size_t)CAND_M * HID];
__device__ float g_Y  [(size_t)T_TOK  * HID];
__device__ unsigned char g_mask[MASK_N];

__device__ bf16 g_Xhi [(size_t)T_TOK  * HID];
__device__ bf16 g_Xlo [(size_t)T_TOK  * HID];
__device__ bf16 g_Chi [(size_t)CAND_M * HID];
__device__ bf16 g_Clo [(size_t)CAND_M * HID];
__device__ bf16 g_Wqhi[(size_t)HID * HID];
__device__ bf16 g_Wqlo[(size_t)HID * HID];
__device__ bf16 g_Wkhi[(size_t)HID * HID];
__device__ bf16 g_Wklo[(size_t)HID * HID];
__device__ bf16 g_Wvhi[(size_t)HID * HID];
__device__ bf16 g_Wvlo[(size_t)HID * HID];
__device__ bf16 g_Wthi[(size_t)FF * HID];
__device__ bf16 g_Wtlo[(size_t)FF * HID];
__device__ bf16 g_Wchi[(size_t)HID * FF];
__device__ bf16 g_Wclo[(size_t)HID * FF];
__device__ bf16 g_CXhi[(size_t)T_TOK * HID];
__device__ bf16 g_CXlo[(size_t)T_TOK * HID];
__device__ bf16 g_Hhi [(size_t)T_TOK * FF];
__device__ bf16 g_Hlo [(size_t)T_TOK * FF];

// ----------------------------------------------------------------------------
// Helpers
// ----------------------------------------------------------------------------
__device__ __forceinline__ uint32_t smem_to_u32(const void* p) {
    uint32_t a;
    asm("{ .reg .u64 t; cvta.to.shared.u64 t, %1; cvt.u32.u64 %0, t; }"
        : "=r"(a) : "l"(p));
    return a;
}

#define CP_ASYNC16(dst_u32, src_ptr) \
    asm volatile("cp.async.cg.shared.global [%0], [%1], 16;" \
                 :: "r"(dst_u32), "l"(src_ptr) : "memory")
#define CP_COMMIT()  asm volatile("cp.async.commit_group;" ::: "memory")
#define CP_WAIT2()   asm volatile("cp.async.wait_group 2;" ::: "memory")

#define LDSM_X4(r0, r1, r2, r3, addr) \
    asm volatile("ldmatrix.sync.aligned.m8n8.x4.shared.b16 {%0,%1,%2,%3}, [%4];" \
                 : "=r"(r0), "=r"(r1), "=r"(r2), "=r"(r3) : "r"(addr))

// m16n8k16 bf16 MMA with fp32 accumulate (baseline PTX, works at compute_103)
__device__ __forceinline__ void mma16816(float* c, const uint32_t* a, const uint32_t* b)
{
    asm volatile(
        "mma.sync.aligned.m16n8k16.row.col.f32.bf16.bf16.f32 "
        "{%0,%1,%2,%3}, {%4,%5,%6,%7}, {%8,%9}, {%0,%1,%2,%3};"
        : "+f"(c[0]), "+f"(c[1]), "+f"(c[2]), "+f"(c[3])
        : "r"(a[0]), "r"(a[1]), "r"(a[2]), "r"(a[3]), "r"(b[0]), "r"(b[1]));
}

__device__ __forceinline__ float gelu_f(float x)
{
    return 0.5f * x * (1.0f + erff(x * 0.70710678118654752440f));
}

// ----------------------------------------------------------------------------
// GEMM:  D[M,N] = (Ahi+Alo)[M,K] @ (Bhi+Blo)[N,K]^T + bias[N]
// 3-term bf16 split, fp32 accumulation via mma.sync.m16n8k16.
// CTA tile 128x128, K-chunk 32, 512 threads (16 warps, warp tile 32x32).
// Fragments via ldmatrix.x4.
//
// 4-STAGE cp.async pipeline (Round 11): prefetch 3 chunks ahead, per-iter
// `cp.async.wait_group 2` (+ unconditional empty commits at the tail so the
// outstanding-group count stays 3). The 2-stage version exposed GMEM latency
// at every chunk boundary (measured ~1280 cyc/kstep/SM vs ~670 smem floor).
// One __syncthreads per chunk: it both publishes the waited cp.async data and
// protects stage (c&3) from being overwritten by iter c+1's prefetch.
// ----------------------------------------------------------------------------
#define SKP         40                      // smem row stride in bf16 (80 B)
#define MAT_BYTES   (128 * SKP * 2)         // 10240 B per matrix tile
#define STAGE_BYTES (4 * MAT_BYTES)         // Ahi,Alo,Bhi,Blo = 40960 B
#define NSTAGE      4
#define GEMM_SMEM_TOTAL (NSTAGE * STAGE_BYTES)   // 163840 B

__global__ void __launch_bounds__(512)
gemm_bf16split(const bf16* __restrict__ Ahi, const bf16* __restrict__ Alo,
               const bf16* __restrict__ Bhi, const bf16* __restrict__ Blo,
               const float* __restrict__ bias,
               float* __restrict__ outF,
               bf16* __restrict__ outHi, bf16* __restrict__ outLo,
               int M, int N, int K, int gelu_flag)
{
    extern __shared__ __align__(16) char sm[];
    const uint32_t smem_u32 = smem_to_u32(sm);
    const int tid  = threadIdx.x;
    const int wid  = tid >> 5;
    const int lane = tid & 31;
    const int bm = blockIdx.y * 128;
    const int bn = blockIdx.x * 128;
    const int wm = (wid >> 2) * 32;     // warp M offset: 0/32/64/96
    const int wn = (wid & 3) * 32;      // warp N offset: 0/32/64/96

    // global->smem loader coords: one 16B segment per matrix per thread
    const int lrow = tid >> 2;          // 0..127
    const int lseg = tid & 3;           // 16B segment within 64B row

    // ldmatrix lane-relative byte offsets (verified mapping, Round 9):
    const int aRow = (lane & 7) + ((lane >> 3) & 1) * 8;
    const int aCol = (lane >> 4) * 8;
    const uint32_t relA0 = (uint32_t)((wm +  0 + aRow) * SKP * 2 + aCol * 2);
    const uint32_t relA1 = (uint32_t)((wm + 16 + aRow) * SKP * 2 + aCol * 2);
    const int bRow = (lane & 7) + (lane >> 4) * 8;
    const int bCol = ((lane >> 3) & 1) * 8;
    const uint32_t relB0 = (uint32_t)((wn +  0 + bRow) * SKP * 2 + bCol * 2);
    const uint32_t relB1 = (uint32_t)((wn + 16 + bRow) * SKP * 2 + bCol * 2);

    float acc[2][4][4];
#pragma unroll
    for (int i = 0; i < 2; i++)
#pragma unroll
        for (int j = 0; j < 4; j++)
#pragma unroll
            for (int r = 0; r < 4; r++) acc[i][j][r] = 0.0f;

    auto prefetch = [&](int k0, int s) {
        const uint32_t sb = smem_u32 + s * STAGE_BYTES;
        const uint32_t so = (uint32_t)(lrow * (SKP * 2) + lseg * 16);
        const size_t ga = (size_t)(bm + lrow) * K + k0 + lseg * 8;
        const size_t gb = (size_t)(bn + lrow) * K + k0 + lseg * 8;
        CP_ASYNC16(sb + 0 * MAT_BYTES + so, Ahi + ga);
        CP_ASYNC16(sb + 1 * MAT_BYTES + so, Alo + ga);
        CP_ASYNC16(sb + 2 * MAT_BYTES + so, Bhi + gb);
        CP_ASYNC16(sb + 3 * MAT_BYTES + so, Blo + gb);
    };

    const int nchunks = K >> 5;   // >= 24 for all our shapes

    // prologue: fill 3 of 4 stages
#pragma unroll
    for (int p = 0; p < NSTAGE - 1; p++) {
        if (p < nchunks) prefetch(p << 5, p);
        CP_COMMIT();
    }

    for (int c = 0; c < nchunks; c++) {
        // wait until at most 2 groups outstanding -> chunk c's group complete
        CP_WAIT2();
        __syncthreads();
        // keep the outstanding-group count at 3 (empty commit at the tail)
        if (c + NSTAGE - 1 < nchunks)
            prefetch((c + NSTAGE - 1) << 5, (c + NSTAGE - 1) & (NSTAGE - 1));
        CP_COMMIT();

        const uint32_t st = smem_u32 + (c & (NSTAGE - 1)) * STAGE_BYTES;

#pragma unroll
        for (int kk = 0; kk < 32; kk += 16) {
            const uint32_t kb = st + kk * 2;
            uint32_t ah[8], al[8], bh[8], bl[8];

            LDSM_X4(ah[0], ah[1], ah[2], ah[3], kb + relA0);
            LDSM_X4(ah[4], ah[5], ah[6], ah[7], kb + relA1);
            LDSM_X4(bh[0], bh[1], bh[2], bh[3], kb + 2 * MAT_BYTES + relB0);
            LDSM_X4(bh[4], bh[5], bh[6], bh[7], kb + 2 * MAT_BYTES + relB1);
            LDSM_X4(al[0], al[1], al[2], al[3], kb + MAT_BYTES + relA0);
            LDSM_X4(al[4], al[5], al[6], al[7], kb + MAT_BYTES + relA1);
            LDSM_X4(bl[0], bl[1], bl[2], bl[3], kb + 3 * MAT_BYTES + relB0);
            LDSM_X4(bl[4], bl[5], bl[6], bl[7], kb + 3 * MAT_BYTES + relB1);

#pragma unroll
            for (int mi = 0; mi < 2; mi++)
#pragma unroll
                for (int ni = 0; ni < 4; ni++)
                    mma16816(acc[mi][ni], &ah[mi * 4], &bh[ni * 2]);   // hi*hi
#pragma unroll
            for (int mi = 0; mi < 2; mi++)
#pragma unroll
                for (int ni = 0; ni < 4; ni++)
                    mma16816(acc[mi][ni], &ah[mi * 4], &bl[ni * 2]);   // hi*lo
#pragma unroll
            for (int mi = 0; mi < 2; mi++)
#pragma unroll
                for (int ni = 0; ni < 4; ni++)
                    mma16816(acc[mi][ni], &al[mi * 4], &bh[ni * 2]);   // lo*hi
        }
    }

    // ------------------------------------------------------------------ epilogue
#pragma unroll
    for (int mi = 0; mi < 2; mi++) {
        const int r0 = bm + wm + mi * 16 + (lane >> 2);
#pragma unroll
        for (int ni = 0; ni < 4; ni++) {
            const int c0 = bn + wn + ni * 8 + (lane & 3) * 2;
            const float b0 = bias[c0], b1 = bias[c0 + 1];
            float v0 = acc[mi][ni][0] + b0;
            float v1 = acc[mi][ni][1] + b1;
            float v2 = acc[mi][ni][2] + b0;
            float v3 = acc[mi][ni][3] + b1;
            if (gelu_flag) {
                v0 = gelu_f(v0); v1 = gelu_f(v1);
                v2 = gelu_f(v2); v3 = gelu_f(v3);
            }
            if (outF) {
                *(float2*)(outF + (size_t)r0 * N + c0)       = make_float2(v0, v1);
                *(float2*)(outF + (size_t)(r0 + 8) * N + c0) = make_float2(v2, v3);
            } else {
                const bf16 h0 = __float2bfloat16(v0);
                const bf16 h1 = __float2bfloat16(v1);
                const bf16 h2 = __float2bfloat16(v2);
                const bf16 h3 = __float2bfloat16(v3);
                bf162 hp0; hp0.x = h0; hp0.y = h1;
                bf162 hp1; hp1.x = h2; hp1.y = h3;
                bf162 lp0; lp0.x = __float2bfloat16(v0 - __bfloat162float(h0));
                lp0.y = __float2bfloat16(v1 - __bfloat162float(h1));
                bf162 lp1; lp1.x = __float2bfloat16(v2 - __bfloat162float(h2));
                lp1.y = __float2bfloat16(v3 - __bfloat162float(h3));
                *(bf162*)(outHi + (size_t)r0 * N + c0)       = hp0;
                *(bf162*)(outHi + (size_t)(r0 + 8) * N + c0) = hp1;
                *(bf162*)(outLo + (size_t)r0 * N + c0)       = lp0;
                *(bf162*)(outLo + (size_t)(r0 + 8) * N + c0) = lp1;
            }
        }
    }
}

// ----------------------------------------------------------------------------
// fp32 -> bf16 hi/lo split
// ----------------------------------------------------------------------------
__global__ __launch_bounds__(256)
void split_kernel(const float* __restrict__ in, bf16* __restrict__ hi,
                  bf16* __restrict__ lo, int n)
{
    const int i = (blockIdx.x * 256 + threadIdx.x) * 4;
    if (i >= n) return;
    const float4 v = *(const float4*)(in + i);
    const bf16 h0 = __float2bfloat16(v.x);
    const bf16 h1 = __float2bfloat16(v.y);
    const bf16 h2 = __float2bfloat16(v.z);
    const bf16 h3 = __float2bfloat16(v.w);
    const bf16 l0 = __float2bfloat16(v.x - __bfloat162float(h0));
    const bf16 l1 = __float2bfloat16(v.y - __bfloat162float(h1));
    const bf16 l2 = __float2bfloat16(v.z - __bfloat162float(h2));
    const bf16 l3 = __float2bfloat16(v.w - __bfloat162float(h3));
    bf162 hp0; hp0.x = h0; hp0.y = h1;
    bf162 hp1; hp1.x = h2; hp1.y = h3;
    bf162 lp0; lp0.x = l0; lp0.y = l1;
    bf162 lp1; lp1.x = l2; lp1.y = l3;
    uint2 hv, lv;
    hv.x = *(const uint32_t*)&hp0; hv.y = *(const uint32_t*)&hp1;
    lv.x = *(const uint32_t*)&lp0; lv.y = *(const uint32_t*)&lp1;
    *(uint2*)(hi + i) = hv;
    *(uint2*)(lo + i) = lv;
}

// ----------------------------------------------------------------------------
// Mask normalization (dtype-robust: bool/uint8, int32, or float32 -> uint8)
// ----------------------------------------------------------------------------
__global__ void mask_norm_kernel(const void* __restrict__ mp)
{
    __shared__ int s_nonbin;
    __shared__ int s_offnz;
    const unsigned char* b = (const unsigned char*)mp;
    if (threadIdx.x == 0) { s_nonbin = 0; s_offnz = 0; }
    __syncthreads();

    int local_nonbin = 0, local_offnz = 0;
    for (int i = threadIdx.x; i < MASK_N; i += blockDim.x) {
        unsigned char v = b[i];
        if (v > 1)                  local_nonbin = 1;
        if ((i & 3) != 0 && v != 0) local_offnz = 1;
    }
    if (local_nonbin) atomicOr(&s_nonbin, 1);
    if (local_offnz)  atomicOr(&s_offnz, 1);
    __syncthreads();

    const int nonbin = s_nonbin, offnz = s_offnz;
    if (nonbin) {
        const float* f = (const float*)mp;
        for (int i = threadIdx.x; i < MASK_N; i += blockDim.x)
            g_mask[i] = (f[i] != 0.0f) ? 1 : 0;
    } else if (offnz) {
        for (int i = threadIdx.x; i < MASK_N; i += blockDim.x)
            g_mask[i] = (b[i] != 0) ? 1 : 0;
    } else {
        const int* ip = (const int*)mp;
        for (int i = threadIdx.x; i < MASK_N; i += blockDim.x)
            g_mask[i] = (ip[i] != 0) ? 1 : 0;
    }
}

// ----------------------------------------------------------------------------
// Attention: one warp per (token, head). Writes CTX directly as bf16 hi/lo.
// ----------------------------------------------------------------------------
__global__ __launch_bounds__(256)
void attn_kernel(const float* __restrict__ Q, const float* __restrict__ Kb,
                 const float* __restrict__ Vb,
                 bf16* __restrict__ CXhi, bf16* __restrict__ CXlo)
{
    const int w    = (blockIdx.x * blockDim.x + threadIdx.x) >> 5;
    const int lane = threadIdx.x & 31;
    if (w >= T_TOK * NH) return;
    const int t = w / NH;
    const int h = w % NH;

    const size_t qoff = (size_t)t * HID + h * HD + lane * 2;
    const float2 q = *(const float2*)(Q + qoff);

    float s[NC];
    unsigned allm = 1;
#pragma unroll
    for (int n = 0; n < NC; n++) {
        const float2 kv = *(const float2*)(Kb + ((size_t)t * NC + n) * HID + h * HD + lane * 2);
        float p = q.x * kv.x + q.y * kv.y;
#pragma unroll
        for (int o = 16; o > 0; o >>= 1)
            p += __shfl_xor_sync(0xffffffffu, p, o);
        const unsigned char mn = g_mask[t * NC + n];
        allm &= (mn != 0);
        s[n] = mn ? 1e-10f : p * 0.125f;
    }

    float mx = s[0];
#pragma unroll
    for (int n = 1; n < NC; n++) mx = fmaxf(mx, s[n]);
    float sum = 0.0f;
#pragma unroll
    for (int n = 0; n < NC; n++) { s[n] = expf(s[n] - mx); sum += s[n]; }
    const float inv = 1.0f / sum;

    float2 c = make_float2(0.0f, 0.0f);
#pragma unroll
    for (int n = 0; n < NC; n++) {
        const float2 vv = *(const float2*)(Vb + ((size_t)t * NC + n) * HID + h * HD + lane * 2);
        const float p = s[n] * inv;
        c.x += p * vv.x;
        c.y += p * vv.y;
    }
    if (allm) { c.x = 0.0f; c.y = 0.0f; }

    const bf16 h0 = __float2bfloat16(c.x);
    const bf16 h1 = __float2bfloat16(c.y);
    const bf16 l0 = __float2bfloat16(c.x - __bfloat162float(h0));
    const bf16 l1 = __float2bfloat16(c.y - __bfloat162float(h1));
    bf162 hp; hp.x = h0; hp.y = h1;
    bf162 lp; lp.x = l0; lp.y = l1;
    *(bf162*)(CXhi + qoff) = hp;
    *(bf162*)(CXlo + qoff) = lp;
}

// ----------------------------------------------------------------------------
// Residual + LayerNorm
// ----------------------------------------------------------------------------
__global__ __launch_bounds__(256)
void ln_kernel(const float* __restrict__ Y, const float* __restrict__ X,
               const float* __restrict__ gamma, const float* __restrict__ beta,
               float* __restrict__ O)
{
    const int t   = blockIdx.x;
    const int tid = threadIdx.x;
    const float* yp = Y + (size_t)t * HID;
    const float* xp = X + (size_t)t * HID;

    float v[3];
    float sum = 0.0f, sq = 0.0f;
#pragma unroll
    for (int i = 0; i < 3; i++) {
        const int idx = tid + i * 256;
        v[i] = yp[idx] + xp[idx];
        sum += v[i];
        sq  += v[i] * v[i];
    }

    const int lane = tid & 31, wid = tid >> 5;
#pragma unroll
    for (int o = 16; o > 0; o >>= 1) {
        sum += __shfl_xor_sync(0xffffffffu, sum, o);
        sq  += __shfl_xor_sync(0xffffffffu, sq,  o);
    }
    __shared__ float rs[8], rq[8];
    if (lane == 0) { rs[wid] = sum; rq[wid] = sq; }
    __syncthreads();
    sum = 0.0f; sq = 0.0f;
#pragma unroll
    for (int i = 0; i < 8; i++) { sum += rs[i]; sq += rq[i]; }

    const float mean = sum * (1.0f / HID);
    const float var  = sq * (1.0f / HID) - mean * mean;
    const float inv  = rsqrtf(var + 1e-12f);

    float* op = O + (size_t)t * HID;
#pragma unroll
    for (int i = 0; i < 3; i++) {
        const int idx = tid + i * 256;
        op[idx] = (v[i] - mean) * inv * gamma[idx] + beta[idx];
    }
}

// ----------------------------------------------------------------------------
// kernel_launch
// Launch order is chosen so the ncu capture (-s 5 -c 1 -> 6th launch)
// profiles the K GEMM: mask, splitC, splitWk, splitWv, splitX, gemmK, ...
// ----------------------------------------------------------------------------
extern "C" void kernel_launch(void* const* d_in, const int* in_sizes, int n_in,
                              void* d_out, int out_size)
{
    const float* X    = (const float*)d_in[0];
    const float* Cand = (const float*)d_in[1];
    const void*  Mask = d_in[2];
    const float* Wq   = (const float*)d_in[3];
    const float* bq   = (const float*)d_in[4];
    const float* Wk   = (const float*)d_in[5];
    const float* bk   = (const float*)d_in[6];
    const float* Wv   = (const float*)d_in[7];
    const float* bv   = (const float*)d_in[8];
    const float* Wt   = (const float*)d_in[9];
    const float* bt   = (const float*)d_in[10];
    const float* Wc   = (const float*)d_in[11];
    const float* bc   = (const float*)d_in[12];
    const float* gam  = (const float*)d_in[13];
    const float* bet  = (const float*)d_in[14];
    float* out = (float*)d_out;

    void *pQ, *pK, *pV, *pY;
    void *pXhi, *pXlo, *pChi, *pClo;
    void *pWqhi, *pWqlo, *pWkhi, *pWklo, *pWvhi, *pWvlo;
    void *pWthi, *pWtlo, *pWchi, *pWclo;
    void *pCXhi, *pCXlo, *pHhi, *pHlo;
    cudaGetSymbolAddress(&pQ, g_Q);     cudaGetSymbolAddress(&pK, g_K);
    cudaGetSymbolAddress(&pV, g_V);     cudaGetSymbolAddress(&pY, g_Y);
    cudaGetSymbolAddress(&pXhi, g_Xhi); cudaGetSymbolAddress(&pXlo, g_Xlo);
    cudaGetSymbolAddress(&pChi, g_Chi); cudaGetSymbolAddress(&pClo, g_Clo);
    cudaGetSymbolAddress(&pWqhi, g_Wqhi); cudaGetSymbolAddress(&pWqlo, g_Wqlo);
    cudaGetSymbolAddress(&pWkhi, g_Wkhi); cudaGetSymbolAddress(&pWklo, g_Wklo);
    cudaGetSymbolAddress(&pWvhi, g_Wvhi); cudaGetSymbolAddress(&pWvlo, g_Wvlo);
    cudaGetSymbolAddress(&pWthi, g_Wthi); cudaGetSymbolAddress(&pWtlo, g_Wtlo);
    cudaGetSymbolAddress(&pWchi, g_Wchi); cudaGetSymbolAddress(&pWclo, g_Wclo);
    cudaGetSymbolAddress(&pCXhi, g_CXhi); cudaGetSymbolAddress(&pCXlo, g_CXlo);
    cudaGetSymbolAddress(&pHhi, g_Hhi);   cudaGetSymbolAddress(&pHlo, g_Hlo);

    cudaFuncSetAttribute(gemm_bf16split,
                         cudaFuncAttributeMaxDynamicSharedMemorySize,
                         GEMM_SMEM_TOTAL);

    // launch 0: mask normalization
    mask_norm_kernel<<<1, 1024>>>(Mask);
    // launches 1-4: splits needed by the K/V GEMMs (+X)
    split_kernel<<<(CAND_M * HID) / 1024, 256>>>(Cand,(bf16*)pChi, (bf16*)pClo, CAND_M * HID);
    split_kernel<<<(HID * HID) / 1024, 256>>>(Wk,     (bf16*)pWkhi,(bf16*)pWklo,HID * HID);
    split_kernel<<<(HID * HID) / 1024, 256>>>(Wv,     (bf16*)pWvhi,(bf16*)pWvlo,HID * HID);
    split_kernel<<<(T_TOK * HID) / 1024, 256>>>(X,    (bf16*)pXhi, (bf16*)pXlo, T_TOK * HID);

    // launch 5 (ncu-profiled): K = Cand @ Wk^T + bk
    {
        dim3 g(HID / 128, CAND_M / 128);
        gemm_bf16split<<<g, 512, GEMM_SMEM_TOTAL>>>(
            (const bf16*)pChi, (const bf16*)pClo,
            (const bf16*)pWkhi,(const bf16*)pWklo, bk,
            (float*)pK, nullptr, nullptr, CAND_M, HID, HID, 0);
        // V = Cand @ Wv^T + bv
        gemm_bf16split<<<g, 512, GEMM_SMEM_TOTAL>>>(
            (const bf16*)pChi, (const bf16*)pClo,
            (const bf16*)pWvhi,(const bf16*)pWvlo, bv,
            (float*)pV, nullptr, nullptr, CAND_M, HID, HID, 0);
    }
    // Q path
    split_kernel<<<(HID * HID) / 1024, 256>>>(Wq, (bf16*)pWqhi,(bf16*)pWqlo, HID * HID);
    {
        dim3 g(HID / 128, T_TOK / 128);
        gemm_bf16split<<<g, 512, GEMM_SMEM_TOTAL>>>(
            (const bf16*)pXhi, (const bf16*)pXlo,
            (const bf16*)pWqhi,(const bf16*)pWqlo, bq,
            (float*)pQ, nullptr, nullptr, T_TOK, HID, HID, 0);
    }
    // attention -> CTX (bf16 hi/lo)
    attn_kernel<<<(T_TOK * NH) / 8, 256>>>((const float*)pQ, (const float*)pK,
                                           (const float*)pV,
                                           (bf16*)pCXhi, (bf16*)pCXlo);
    // H = gelu(CTX @ Wt^T + bt)
    split_kernel<<<(FF * HID) / 1024, 256>>>(Wt, (bf16*)pWthi,(bf16*)pWtlo, FF * HID);
    {
        dim3 g(FF / 128, T_TOK / 128);
        gemm_bf16split<<<g, 512, GEMM_SMEM_TOTAL>>>(
            (const bf16*)pCXhi,(const bf16*)pCXlo,
            (const bf16*)pWthi,(const bf16*)pWtlo, bt,
            nullptr, (bf16*)pHhi, (bf16*)pHlo, T_TOK, FF, HID, 1);
    }
    // Y = H @ Wc^T + bc
    split_kernel<<<(HID * FF) / 1024, 256>>>(Wc, (bf16*)pWchi,(bf16*)pWclo, HID * FF);
    {
        dim3 g(HID / 128, T_TOK / 128);
        gemm_bf16split<<<g, 512, GEMM_SMEM_TOTAL>>>(
            (const bf16*)pHhi, (const bf16*)pHlo,
            (const bf16*)pWchi,(const bf16*)pWclo, bc,
            (float*)pY, nullptr, nullptr, T_TOK, HID, FF, 0);
    }
    // out = LayerNorm(Y + X)
    ln_kernel<<<T_TOK, 256>>>((const float*)pY, X, gam, bet, out);
}

// round 13
// speedup vs baseline: 1.3203x; 1.3203x over previous
#include <cuda_runtime.h>
#include <cuda_fp16.h>
#include <cstdint>

// ----------------------------------------------------------------------------
// Problem constants: B=4, S=2048 -> T=8192 tokens, HID=768, NH=12, HD=64,
// NC=8 candidates, FF=3072
// ----------------------------------------------------------------------------
#define T_TOK   8192
#define HID     768
#define NH      12
#define HD      64
#define NC      8
#define FF      3072
#define CAND_M  (T_TOK * NC)   // 65536
#define MASK_N  (T_TOK * NC)   // 65536

typedef __half  f16;
typedef __half2 f162;

// ----------------------------------------------------------------------------
// Scratch (device globals -- no allocation allowed anywhere)
// ----------------------------------------------------------------------------
__device__ float g_Q  [(size_t)T_TOK  * HID];
__device__ float g_K  [(size_t)CAND_M * HID];
__device__ float g_V  [(size_t)CAND_M * HID];
__device__ float g_Y  [(size_t)T_TOK  * HID];
__device__ unsigned char g_mask[MASK_N];

// fp16 activation hi/lo splits (A-side of every GEMM)
__device__ f16 g_Xhi [(size_t)T_TOK  * HID];
__device__ f16 g_Xlo [(size_t)T_TOK  * HID];
__device__ f16 g_Chi [(size_t)CAND_M * HID];
__device__ f16 g_Clo [(size_t)CAND_M * HID];
__device__ f16 g_CXhi[(size_t)T_TOK * HID];
__device__ f16 g_CXlo[(size_t)T_TOK * HID];
__device__ f16 g_Hhi [(size_t)T_TOK * FF];
__device__ f16 g_Hlo [(size_t)T_TOK * FF];
// fp16 single-precision weights (B-side)
__device__ f16 g_Wq16[(size_t)HID * HID];
__device__ f16 g_Wk16[(size_t)HID * HID];
__device__ f16 g_Wv16[(size_t)HID * HID];
__device__ f16 g_Wt16[(size_t)FF * HID];
__device__ f16 g_Wc16[(size_t)HID * FF];

// ----------------------------------------------------------------------------
// Helpers
// ----------------------------------------------------------------------------
__device__ __forceinline__ uint32_t smem_to_u32(const void* p) {
    uint32_t a;
    asm("{ .reg .u64 t; cvta.to.shared.u64 t, %1; cvt.u32.u64 %0, t; }"
        : "=r"(a) : "l"(p));
    return a;
}

#define CP_ASYNC16(dst_u32, src_ptr) \
    asm volatile("cp.async.cg.shared.global [%0], [%1], 16;" \
                 :: "r"(dst_u32), "l"(src_ptr) : "memory")
#define CP_COMMIT()  asm volatile("cp.async.commit_group;" ::: "memory")
#define CP_WAIT2()   asm volatile("cp.async.wait_group 2;" ::: "memory")

#define LDSM_X4(r0, r1, r2, r3, addr) \
    asm volatile("ldmatrix.sync.aligned.m8n8.x4.shared.b16 {%0,%1,%2,%3}, [%4];" \
                 : "=r"(r0), "=r"(r1), "=r"(r2), "=r"(r3) : "r"(addr))

// m16n8k16 fp16 MMA with fp32 accumulate (baseline PTX, works at compute_103)
__device__ __forceinline__ void mma16816(float* c, const uint32_t* a, const uint32_t* b)
{
    asm volatile(
        "mma.sync.aligned.m16n8k16.row.col.f32.f16.f16.f32 "
        "{%0,%1,%2,%3}, {%4,%5,%6,%7}, {%8,%9}, {%0,%1,%2,%3};"
        : "+f"(c[0]), "+f"(c[1]), "+f"(c[2]), "+f"(c[3])
        : "r"(a[0]), "r"(a[1]), "r"(a[2]), "r"(a[3]), "r"(b[0]), "r"(b[1]));
}

__device__ __forceinline__ float gelu_f(float x)
{
    return 0.5f * x * (1.0f + erff(x * 0.70710678118654752440f));
}

// ----------------------------------------------------------------------------
// GEMM:  D[M,N] = (Ahi+Alo)[M,K] @ B[N,K]^T + bias[N]
// 2-term fp16 split (Ah*B + Al*B), fp32 accumulation via mma.sync.m16n8k16.
// A = activations in fp16 hi/lo (~22-bit effective); B = weights in single
// fp16 (11-bit mantissa -> ~2^-12 relative error, well under the 1e-3 budget).
// Replaces the 3-term bf16 scheme: 16 MMAs/kstep/warp instead of 24 (the
// fallback-HMMA tensor pipe measured saturated at ~13 cyc/MMA/SMSP), and
// 3 smem tiles per stage instead of 4.
// CTA tile 128x128, K-chunk 32, 512 threads (16 warps, warp tile 32x32).
// 4-stage cp.async pipeline; fragments via ldmatrix.x4; SKP=40 conflict-free.
// ----------------------------------------------------------------------------
#define SKP         40                      // smem row stride in b16 (80 B)
#define MAT_BYTES   (128 * SKP * 2)         // 10240 B per matrix tile
#define STAGE_BYTES (3 * MAT_BYTES)         // Ahi,Alo,B = 30720 B
#define NSTAGE      4
#define GEMM_SMEM_TOTAL (NSTAGE * STAGE_BYTES)   // 122880 B

__global__ void __launch_bounds__(512)
gemm_f16split(const f16* __restrict__ Ahi, const f16* __restrict__ Alo,
              const f16* __restrict__ B,
              const float* __restrict__ bias,
              float* __restrict__ outF,
              f16* __restrict__ outHi, f16* __restrict__ outLo,
              int M, int N, int K, int gelu_flag)
{
    extern __shared__ __align__(16) char sm[];
    const uint32_t smem_u32 = smem_to_u32(sm);
    const int tid  = threadIdx.x;
    const int wid  = tid >> 5;
    const int lane = tid & 31;
    const int bm = blockIdx.y * 128;
    const int bn = blockIdx.x * 128;
    const int wm = (wid >> 2) * 32;     // warp M offset: 0/32/64/96
    const int wn = (wid & 3) * 32;      // warp N offset: 0/32/64/96

    // global->smem loader coords: one 16B segment per matrix per thread
    const int lrow = tid >> 2;          // 0..127
    const int lseg = tid & 3;           // 16B segment within 64B row

    // ldmatrix lane-relative byte offsets (verified mapping, Round 9):
    const int aRow = (lane & 7) + ((lane >> 3) & 1) * 8;
    const int aCol = (lane >> 4) * 8;
    const uint32_t relA0 = (uint32_t)((wm +  0 + aRow) * SKP * 2 + aCol * 2);
    const uint32_t relA1 = (uint32_t)((wm + 16 + aRow) * SKP * 2 + aCol * 2);
    const int bRow = (lane & 7) + (lane >> 4) * 8;
    const int bCol = ((lane >> 3) & 1) * 8;
    const uint32_t relB0 = (uint32_t)((wn +  0 + bRow) * SKP * 2 + bCol * 2);
    const uint32_t relB1 = (uint32_t)((wn + 16 + bRow) * SKP * 2 + bCol * 2);

    float acc[2][4][4];
#pragma unroll
    for (int i = 0; i < 2; i++)
#pragma unroll
        for (int j = 0; j < 4; j++)
#pragma unroll
            for (int r = 0; r < 4; r++) acc[i][j][r] = 0.0f;

    auto prefetch = [&](int k0, int s) {
        const uint32_t sb = smem_u32 + s * STAGE_BYTES;
        const uint32_t so = (uint32_t)(lrow * (SKP * 2) + lseg * 16);
        const size_t ga = (size_t)(bm + lrow) * K + k0 + lseg * 8;
        const size_t gb = (size_t)(bn + lrow) * K + k0 + lseg * 8;
        CP_ASYNC16(sb + 0 * MAT_BYTES + so, Ahi + ga);
        CP_ASYNC16(sb + 1 * MAT_BYTES + so, Alo + ga);
        CP_ASYNC16(sb + 2 * MAT_BYTES + so, B   + gb);
    };

    const int nchunks = K >> 5;

    // prologue: fill 3 of 4 stages
#pragma unroll
    for (int p = 0; p < NSTAGE - 1; p++) {
        if (p < nchunks) prefetch(p << 5, p);
        CP_COMMIT();
    }

    for (int c = 0; c < nchunks; c++) {
        CP_WAIT2();
        __syncthreads();
        if (c + NSTAGE - 1 < nchunks)
            prefetch((c + NSTAGE - 1) << 5, (c + NSTAGE - 1) & (NSTAGE - 1));
        CP_COMMIT();

        const uint32_t st = smem_u32 + (c & (NSTAGE - 1)) * STAGE_BYTES;

#pragma unroll
        for (int kk = 0; kk < 32; kk += 16) {
            const uint32_t kb = st + kk * 2;
            uint32_t ah[8], al[8], bf[8];

            LDSM_X4(ah[0], ah[1], ah[2], ah[3], kb + relA0);
            LDSM_X4(ah[4], ah[5], ah[6], ah[7], kb + relA1);
            LDSM_X4(bf[0], bf[1], bf[2], bf[3], kb + 2 * MAT_BYTES + relB0);
            LDSM_X4(bf[4], bf[5], bf[6], bf[7], kb + 2 * MAT_BYTES + relB1);
            LDSM_X4(al[0], al[1], al[2], al[3], kb + MAT_BYTES + relA0);
            LDSM_X4(al[4], al[5], al[6], al[7], kb + MAT_BYTES + relA1);

#pragma unroll
            for (int mi = 0; mi < 2; mi++)
#pragma unroll
                for (int ni = 0; ni < 4; ni++)
                    mma16816(acc[mi][ni], &ah[mi * 4], &bf[ni * 2]);   // hi*B
#pragma unroll
            for (int mi = 0; mi < 2; mi++)
#pragma unroll
                for (int ni = 0; ni < 4; ni++)
                    mma16816(acc[mi][ni], &al[mi * 4], &bf[ni * 2]);   // lo*B
        }
    }

    // ------------------------------------------------------------------ epilogue
#pragma unroll
    for (int mi = 0; mi < 2; mi++) {
        const int r0 = bm + wm + mi * 16 + (lane >> 2);
#pragma unroll
        for (int ni = 0; ni < 4; ni++) {
            const int c0 = bn + wn + ni * 8 + (lane & 3) * 2;
            const float b0 = bias[c0], b1 = bias[c0 + 1];
            float v0 = acc[mi][ni][0] + b0;
            float v1 = acc[mi][ni][1] + b1;
            float v2 = acc[mi][ni][2] + b0;
            float v3 = acc[mi][ni][3] + b1;
            if (gelu_flag) {
                v0 = gelu_f(v0); v1 = gelu_f(v1);
                v2 = gelu_f(v2); v3 = gelu_f(v3);
            }
            if (outF) {
                *(float2*)(outF + (size_t)r0 * N + c0)       = make_float2(v0, v1);
                *(float2*)(outF + (size_t)(r0 + 8) * N + c0) = make_float2(v2, v3);
            } else {
                const f16 h0 = __float2half(v0);
                const f16 h1 = __float2half(v1);
                const f16 h2 = __float2half(v2);
                const f16 h3 = __float2half(v3);
                f162 hp0; hp0.x = h0; hp0.y = h1;
                f162 hp1; hp1.x = h2; hp1.y = h3;
                f162 lp0; lp0.x = __float2half(v0 - __half2float(h0));
                lp0.y = __float2half(v1 - __half2float(h1));
                f162 lp1; lp1.x = __float2half(v2 - __half2float(h2));
                lp1.y = __float2half(v3 - __half2float(h3));
                *(f162*)(outHi + (size_t)r0 * N + c0)       = hp0;
                *(f162*)(outHi + (size_t)(r0 + 8) * N + c0) = hp1;
                *(f162*)(outLo + (size_t)r0 * N + c0)       = lp0;
                *(f162*)(outLo + (size_t)(r0 + 8) * N + c0) = lp1;
            }
        }
    }
}

// ----------------------------------------------------------------------------
// fp32 -> fp16 hi/lo split (activations)
// ----------------------------------------------------------------------------
__global__ __launch_bounds__(256)
void split_kernel(const float* __restrict__ in, f16* __restrict__ hi,
                  f16* __restrict__ lo, int n)
{
    const int i = (blockIdx.x * 256 + threadIdx.x) * 4;
    if (i >= n) return;
    const float4 v = *(const float4*)(in + i);
    const f16 h0 = __float2half(v.x);
    const f16 h1 = __float2half(v.y);
    const f16 h2 = __float2half(v.z);
    const f16 h3 = __float2half(v.w);
    f162 hp0; hp0.x = h0; hp0.y = h1;
    f162 hp1; hp1.x = h2; hp1.y = h3;
    f162 lp0; lp0.x = __float2half(v.x - __half2float(h0));
    lp0.y = __float2half(v.y - __half2float(h1));
    f162 lp1; lp1.x = __float2half(v.z - __half2float(h2));
    lp1.y = __float2half(v.w - __half2float(h3));
    uint2 hv, lv;
    hv.x = *(const uint32_t*)&hp0; hv.y = *(const uint32_t*)&hp1;
    lv.x = *(const uint32_t*)&lp0; lv.y = *(const uint32_t*)&lp1;
    *(uint2*)(hi + i) = hv;
    *(uint2*)(lo + i) = lv;
}

// ----------------------------------------------------------------------------
// fp32 -> fp16 single (weights)
// ----------------------------------------------------------------------------
__global__ __launch_bounds__(256)
void half_kernel(const float* __restrict__ in, f16* __restrict__ out, int n)
{
    const int i = (blockIdx.x * 256 + threadIdx.x) * 4;
    if (i >= n) return;
    const float4 v = *(const float4*)(in + i);
    f162 p0; p0.x = __float2half(v.x); p0.y = __float2half(v.y);
    f162 p1; p1.x = __float2half(v.z); p1.y = __float2half(v.w);
    uint2 pv;
    pv.x = *(const uint32_t*)&p0; pv.y = *(const uint32_t*)&p1;
    *(uint2*)(out + i) = pv;
}

// ----------------------------------------------------------------------------
// Mask normalization (dtype-robust: bool/uint8, int32, or float32 -> uint8)
// ----------------------------------------------------------------------------
__global__ void mask_norm_kernel(const void* __restrict__ mp)
{
    __shared__ int s_nonbin;
    __shared__ int s_offnz;
    const unsigned char* b = (const unsigned char*)mp;
    if (threadIdx.x == 0) { s_nonbin = 0; s_offnz = 0; }
    __syncthreads();

    int local_nonbin = 0, local_offnz = 0;
    for (int i = threadIdx.x; i < MASK_N; i += blockDim.x) {
        unsigned char v = b[i];
        if (v > 1)                  local_nonbin = 1;
        if ((i & 3) != 0 && v != 0) local_offnz = 1;
    }
    if (local_nonbin) atomicOr(&s_nonbin, 1);
    if (local_offnz)  atomicOr(&s_offnz, 1);
    __syncthreads();

    const int nonbin = s_nonbin, offnz = s_offnz;
    if (nonbin) {
        const float* f = (const float*)mp;
        for (int i = threadIdx.x; i < MASK_N; i += blockDim.x)
            g_mask[i] = (f[i] != 0.0f) ? 1 : 0;
    } else if (offnz) {
        for (int i = threadIdx.x; i < MASK_N; i += blockDim.x)
            g_mask[i] = (b[i] != 0) ? 1 : 0;
    } else {
        const int* ip = (const int*)mp;
        for (int i = threadIdx.x; i < MASK_N; i += blockDim.x)
            g_mask[i] = (ip[i] != 0) ? 1 : 0;
    }
}

// ----------------------------------------------------------------------------
// Attention: one warp per (token, head). Writes CTX directly as fp16 hi/lo.
// ----------------------------------------------------------------------------
__global__ __launch_bounds__(256)
void attn_kernel(const float* __restrict__ Q, const float* __restrict__ Kb,
                 const float* __restrict__ Vb,
                 f16* __restrict__ CXhi, f16* __restrict__ CXlo)
{
    const int w    = (blockIdx.x * blockDim.x + threadIdx.x) >> 5;
    const int lane = threadIdx.x & 31;
    if (w >= T_TOK * NH) return;
    const int t = w / NH;
    const int h = w % NH;

    const size_t qoff = (size_t)t * HID + h * HD + lane * 2;
    const float2 q = *(const float2*)(Q + qoff);

    float s[NC];
    unsigned allm = 1;
#pragma unroll
    for (int n = 0; n < NC; n++) {
        const float2 kv = *(const float2*)(Kb + ((size_t)t * NC + n) * HID + h * HD + lane * 2);
        float p = q.x * kv.x + q.y * kv.y;
#pragma unroll
        for (int o = 16; o > 0; o >>= 1)
            p += __shfl_xor_sync(0xffffffffu, p, o);
        const unsigned char mn = g_mask[t * NC + n];
        allm &= (mn != 0);
        s[n] = mn ? 1e-10f : p * 0.125f;
    }

    float mx = s[0];
#pragma unroll
    for (int n = 1; n < NC; n++) mx = fmaxf(mx, s[n]);
    float sum = 0.0f;
#pragma unroll
    for (int n = 0; n < NC; n++) { s[n] = expf(s[n] - mx); sum += s[n]; }
    const float inv = 1.0f / sum;

    float2 c = make_float2(0.0f, 0.0f);
#pragma unroll
    for (int n = 0; n < NC; n++) {
        const float2 vv = *(const float2*)(Vb + ((size_t)t * NC + n) * HID + h * HD + lane * 2);
        const float p = s[n] * inv;
        c.x += p * vv.x;
        c.y += p * vv.y;
    }
    if (allm) { c.x = 0.0f; c.y = 0.0f; }

    const f16 h0 = __float2half(c.x);
    const f16 h1 = __float2half(c.y);
    f162 hp; hp.x = h0; hp.y = h1;
    f162 lp; lp.x = __float2half(c.x - __half2float(h0));
    lp.y = __float2half(c.y - __half2float(h1));
    *(f162*)(CXhi + qoff) = hp;
    *(f162*)(CXlo + qoff) = lp;
}

// ----------------------------------------------------------------------------
// Residual + LayerNorm
// ----------------------------------------------------------------------------
__global__ __launch_bounds__(256)
void ln_kernel(const float* __restrict__ Y, const float* __restrict__ X,
               const float* __restrict__ gamma, const float* __restrict__ beta,
               float* __restrict__ O)
{
    const int t   = blockIdx.x;
    const int tid = threadIdx.x;
    const float* yp = Y + (size_t)t * HID;
    const float* xp = X + (size_t)t * HID;

    float v[3];
    float sum = 0.0f, sq = 0.0f;
#pragma unroll
    for (int i = 0; i < 3; i++) {
        const int idx = tid + i * 256;
        v[i] = yp[idx] + xp[idx];
        sum += v[i];
        sq  += v[i] * v[i];
    }

    const int lane = tid & 31, wid = tid >> 5;
#pragma unroll
    for (int o = 16; o > 0; o >>= 1) {
        sum += __shfl_xor_sync(0xffffffffu, sum, o);
        sq  += __shfl_xor_sync(0xffffffffu, sq,  o);
    }
    __shared__ float rs[8], rq[8];
    if (lane == 0) { rs[wid] = sum; rq[wid] = sq; }
    __syncthreads();
    sum = 0.0f; sq = 0.0f;
#pragma unroll
    for (int i = 0; i < 8; i++) { sum += rs[i]; sq += rq[i]; }

    const float mean = sum * (1.0f / HID);
    const float var  = sq * (1.0f / HID) - mean * mean;
    const float inv  = rsqrtf(var + 1e-12f);

    float* op = O + (size_t)t * HID;
#pragma unroll
    for (int i = 0; i < 3; i++) {
        const int idx = tid + i * 256;
        op[idx] = (v[i] - mean) * inv * gamma[idx] + beta[idx];
    }
}

// ----------------------------------------------------------------------------
// kernel_launch
// ----------------------------------------------------------------------------
extern "C" void kernel_launch(void* const* d_in, const int* in_sizes, int n_in,
                              void* d_out, int out_size)
{
    const float* X    = (const float*)d_in[0];
    const float* Cand = (const float*)d_in[1];
    const void*  Mask = d_in[2];
    const float* Wq   = (const float*)d_in[3];
    const float* bq   = (const float*)d_in[4];
    const float* Wk   = (const float*)d_in[5];
    const float* bk   = (const float*)d_in[6];
    const float* Wv   = (const float*)d_in[7];
    const float* bv   = (const float*)d_in[8];
    const float* Wt   = (const float*)d_in[9];
    const float* bt   = (const float*)d_in[10];
    const float* Wc   = (const float*)d_in[11];
    const float* bc   = (const float*)d_in[12];
    const float* gam  = (const float*)d_in[13];
    const float* bet  = (const float*)d_in[14];
    float* out = (float*)d_out;

    void *pQ, *pK, *pV, *pY;
    void *pXhi, *pXlo, *pChi, *pClo, *pCXhi, *pCXlo, *pHhi, *pHlo;
    void *pWq, *pWk, *pWv, *pWt, *pWc;
    cudaGetSymbolAddress(&pQ, g_Q);     cudaGetSymbolAddress(&pK, g_K);
    cudaGetSymbolAddress(&pV, g_V);     cudaGetSymbolAddress(&pY, g_Y);
    cudaGetSymbolAddress(&pXhi, g_Xhi); cudaGetSymbolAddress(&pXlo, g_Xlo);
    cudaGetSymbolAddress(&pChi, g_Chi); cudaGetSymbolAddress(&pClo, g_Clo);
    cudaGetSymbolAddress(&pCXhi, g_CXhi); cudaGetSymbolAddress(&pCXlo, g_CXlo);
    cudaGetSymbolAddress(&pHhi, g_Hhi);   cudaGetSymbolAddress(&pHlo, g_Hlo);
    cudaGetSymbolAddress(&pWq, g_Wq16); cudaGetSymbolAddress(&pWk, g_Wk16);
    cudaGetSymbolAddress(&pWv, g_Wv16); cudaGetSymbolAddress(&pWt, g_Wt16);
    cudaGetSymbolAddress(&pWc, g_Wc16);

    cudaFuncSetAttribute(gemm_f16split,
                         cudaFuncAttributeMaxDynamicSharedMemorySize,
                         GEMM_SMEM_TOTAL);

    // launch 0: mask normalization
    mask_norm_kernel<<<1, 1024>>>(Mask);
    // launches 1-4: conversions needed by the K/V GEMMs (+X)
    split_kernel<<<(CAND_M * HID) / 1024, 256>>>(Cand,(f16*)pChi, (f16*)pClo, CAND_M * HID);
    half_kernel<<<(HID * HID) / 1024, 256>>>(Wk, (f16*)pWk, HID * HID);
    half_kernel<<<(HID * HID) / 1024, 256>>>(Wv, (f16*)pWv, HID * HID);
    split_kernel<<<(T_TOK * HID) / 1024, 256>>>(X, (f16*)pXhi, (f16*)pXlo, T_TOK * HID);

    // launch 5 (ncu target): K = Cand @ Wk^T + bk
    {
        dim3 g(HID / 128, CAND_M / 128);
        gemm_f16split<<<g, 512, GEMM_SMEM_TOTAL>>>(
            (const f16*)pChi, (const f16*)pClo, (const f16*)pWk, bk,
            (float*)pK, nullptr, nullptr, CAND_M, HID, HID, 0);
        gemm_f16split<<<g, 512, GEMM_SMEM_TOTAL>>>(
            (const f16*)pChi, (const f16*)pClo, (const f16*)pWv, bv,
            (float*)pV, nullptr, nullptr, CAND_M, HID, HID, 0);
    }
    // Q path
    half_kernel<<<(HID * HID) / 1024, 256>>>(Wq, (f16*)pWq, HID * HID);
    {
        dim3 g(HID / 128, T_TOK / 128);
        gemm_f16split<<<g, 512, GEMM_SMEM_TOTAL>>>(
            (const f16*)pXhi, (const f16*)pXlo, (const f16*)pWq, bq,
            (float*)pQ, nullptr, nullptr, T_TOK, HID, HID, 0);
    }
    // attention -> CTX (fp16 hi/lo)
    attn_kernel<<<(T_TOK * NH) / 8, 256>>>((const float*)pQ, (const float*)pK,
                                           (const float*)pV,
                                           (f16*)pCXhi, (f16*)pCXlo);
    // H = gelu(CTX @ Wt^T + bt)
    half_kernel<<<(FF * HID) / 1024, 256>>>(Wt, (f16*)pWt, FF * HID);
    {
        dim3 g(FF / 128, T_TOK / 128);
        gemm_f16split<<<g, 512, GEMM_SMEM_TOTAL>>>(
            (const f16*)pCXhi, (const f16*)pCXlo, (const f16*)pWt, bt,
            nullptr, (f16*)pHhi, (f16*)pHlo, T_TOK, FF, HID, 1);
    }
    // Y = H @ Wc^T + bc
    half_kernel<<<(HID * FF) / 1024, 256>>>(Wc, (f16*)pWc, HID * FF);
    {
        dim3 g(HID / 128, T_TOK / 128);
        gemm_f16split<<<g, 512, GEMM_SMEM_TOTAL>>>(
            (const f16*)pHhi, (const f16*)pHlo, (const f16*)pWc, bc,
            (float*)pY, nullptr, nullptr, T_TOK, HID, FF, 0);
    }
    // out = LayerNorm(Y + X)
    ln_kernel<<<T_TOK, 256>>>((const float*)pY, X, gam, bet, out);
}

// round 14
// speedup vs baseline: 2.3220x; 1.7586x over previous
#include <cuda_runtime.h>
#include <cuda_fp16.h>
#include <cstdint>

// ----------------------------------------------------------------------------
// Problem constants: B=4, S=2048 -> T=8192 tokens, HID=768, NH=12, HD=64,
// NC=8 candidates, FF=3072
// ----------------------------------------------------------------------------
#define T_TOK   8192
#define HID     768
#define NH      12
#define HD      64
#define NC      8
#define FF      3072
#define CAND_M  (T_TOK * NC)   // 65536
#define MASK_N  (T_TOK * NC)   // 65536

typedef __half  f16;
typedef __half2 f162;

// ----------------------------------------------------------------------------
// Scratch (device globals -- no allocation allowed anywhere)
// ----------------------------------------------------------------------------
__device__ float g_Q  [(size_t)T_TOK  * HID];
__device__ float g_K  [(size_t)CAND_M * HID];
__device__ float g_V  [(size_t)CAND_M * HID];
__device__ float g_Y  [(size_t)T_TOK  * HID];
__device__ unsigned char g_mask[MASK_N];

// fp16 operands (single precision per side; calibrated vs Round-12: each
// fp16-rounded operand contributes ~1.4e-5 end-to-end rel_err)
__device__ f16 g_X16 [(size_t)T_TOK  * HID];
__device__ f16 g_C16 [(size_t)CAND_M * HID];
__device__ f16 g_CX16[(size_t)T_TOK * HID];
__device__ f16 g_H16 [(size_t)T_TOK * FF];
__device__ f16 g_Wq16[(size_t)HID * HID];
__device__ f16 g_Wk16[(size_t)HID * HID];
__device__ f16 g_Wv16[(size_t)HID * HID];
__device__ f16 g_Wt16[(size_t)FF * HID];
__device__ f16 g_Wc16[(size_t)HID * FF];

// ----------------------------------------------------------------------------
// Helpers
// ----------------------------------------------------------------------------
__device__ __forceinline__ uint32_t smem_to_u32(const void* p) {
    uint32_t a;
    asm("{ .reg .u64 t; cvta.to.shared.u64 t, %1; cvt.u32.u64 %0, t; }"
        : "=r"(a) : "l"(p));
    return a;
}

#define CP_ASYNC16(dst_u32, src_ptr) \
    asm volatile("cp.async.cg.shared.global [%0], [%1], 16;" \
                 :: "r"(dst_u32), "l"(src_ptr) : "memory")
#define CP_COMMIT()  asm volatile("cp.async.commit_group;" ::: "memory")
#define CP_WAIT2()   asm volatile("cp.async.wait_group 2;" ::: "memory")

#define LDSM_X4(r0, r1, r2, r3, addr) \
    asm volatile("ldmatrix.sync.aligned.m8n8.x4.shared.b16 {%0,%1,%2,%3}, [%4];" \
                 : "=r"(r0), "=r"(r1), "=r"(r2), "=r"(r3) : "r"(addr))

// m16n8k16 fp16 MMA with fp32 accumulate (baseline PTX, works at compute_103)
__device__ __forceinline__ void mma16816(float* c, const uint32_t* a, const uint32_t* b)
{
    asm volatile(
        "mma.sync.aligned.m16n8k16.row.col.f32.f16.f16.f32 "
        "{%0,%1,%2,%3}, {%4,%5,%6,%7}, {%8,%9}, {%0,%1,%2,%3};"
        : "+f"(c[0]), "+f"(c[1]), "+f"(c[2]), "+f"(c[3])
        : "r"(a[0]), "r"(a[1]), "r"(a[2]), "r"(a[3]), "r"(b[0]), "r"(b[1]));
}

__device__ __forceinline__ float gelu_f(float x)
{
    return 0.5f * x * (1.0f + erff(x * 0.70710678118654752440f));
}

// ----------------------------------------------------------------------------
// GEMM:  D[M,N] = A[M,K] @ B[N,K]^T + bias[N]   (A,B fp16; fp32 accumulate)
// Single-term fp16: 8 MMAs/kstep/warp (the fallback-HMMA tensor pipe measured
// saturated at ~13 cyc/MMA/SMSP in Rounds 10-12; time scales with MMA count).
// CTA tile 128x128, K-chunk 32, 512 threads (16 warps, warp tile 32x32).
// 4-stage cp.async pipeline; fragments via ldmatrix.x4; SKP=40 conflict-free.
// Epilogue: fp32 out (outF) OR single fp16 out (outH); optional exact GELU.
// ----------------------------------------------------------------------------
#define SKP         40                      // smem row stride in b16 (80 B)
#define MAT_BYTES   (128 * SKP * 2)         // 10240 B per matrix tile
#define STAGE_BYTES (2 * MAT_BYTES)         // A,B = 20480 B
#define NSTAGE      4
#define GEMM_SMEM_TOTAL (NSTAGE * STAGE_BYTES)   // 81920 B

__global__ void __launch_bounds__(512)
gemm_f16(const f16* __restrict__ A, const f16* __restrict__ B,
         const float* __restrict__ bias,
         float* __restrict__ outF, f16* __restrict__ outH,
         int M, int N, int K, int gelu_flag)
{
    extern __shared__ __align__(16) char sm[];
    const uint32_t smem_u32 = smem_to_u32(sm);
    const int tid  = threadIdx.x;
    const int wid  = tid >> 5;
    const int lane = tid & 31;
    const int bm = blockIdx.y * 128;
    const int bn = blockIdx.x * 128;
    const int wm = (wid >> 2) * 32;     // warp M offset: 0/32/64/96
    const int wn = (wid & 3) * 32;      // warp N offset: 0/32/64/96

    // global->smem loader coords: one 16B segment per matrix per thread
    const int lrow = tid >> 2;          // 0..127
    const int lseg = tid & 3;           // 16B segment within 64B row

    // ldmatrix lane-relative byte offsets (verified mapping, Round 9):
    const int aRow = (lane & 7) + ((lane >> 3) & 1) * 8;
    const int aCol = (lane >> 4) * 8;
    const uint32_t relA0 = (uint32_t)((wm +  0 + aRow) * SKP * 2 + aCol * 2);
    const uint32_t relA1 = (uint32_t)((wm + 16 + aRow) * SKP * 2 + aCol * 2);
    const int bRow = (lane & 7) + (lane >> 4) * 8;
    const int bCol = ((lane >> 3) & 1) * 8;
    const uint32_t relB0 = (uint32_t)((wn +  0 + bRow) * SKP * 2 + bCol * 2);
    const uint32_t relB1 = (uint32_t)((wn + 16 + bRow) * SKP * 2 + bCol * 2);

    float acc[2][4][4];
#pragma unroll
    for (int i = 0; i < 2; i++)
#pragma unroll
        for (int j = 0; j < 4; j++)
#pragma unroll
            for (int r = 0; r < 4; r++) acc[i][j][r] = 0.0f;

    auto prefetch = [&](int k0, int s) {
        const uint32_t sb = smem_u32 + s * STAGE_BYTES;
        const uint32_t so = (uint32_t)(lrow * (SKP * 2) + lseg * 16);
        const size_t ga = (size_t)(bm + lrow) * K + k0 + lseg * 8;
        const size_t gb = (size_t)(bn + lrow) * K + k0 + lseg * 8;
        CP_ASYNC16(sb + so, A + ga);
        CP_ASYNC16(sb + MAT_BYTES + so, B + gb);
    };

    const int nchunks = K >> 5;

    // prologue: fill 3 of 4 stages
#pragma unroll
    for (int p = 0; p < NSTAGE - 1; p++) {
        if (p < nchunks) prefetch(p << 5, p);
        CP_COMMIT();
    }

    for (int c = 0; c < nchunks; c++) {
        CP_WAIT2();
        __syncthreads();
        if (c + NSTAGE - 1 < nchunks)
            prefetch((c + NSTAGE - 1) << 5, (c + NSTAGE - 1) & (NSTAGE - 1));
        CP_COMMIT();

        const uint32_t st = smem_u32 + (c & (NSTAGE - 1)) * STAGE_BYTES;

#pragma unroll
        for (int kk = 0; kk < 32; kk += 16) {
            const uint32_t kb = st + kk * 2;
            uint32_t af[8], bf[8];

            LDSM_X4(af[0], af[1], af[2], af[3], kb + relA0);
            LDSM_X4(af[4], af[5], af[6], af[7], kb + relA1);
            LDSM_X4(bf[0], bf[1], bf[2], bf[3], kb + MAT_BYTES + relB0);
            LDSM_X4(bf[4], bf[5], bf[6], bf[7], kb + MAT_BYTES + relB1);

#pragma unroll
            for (int mi = 0; mi < 2; mi++)
#pragma unroll
                for (int ni = 0; ni < 4; ni++)
                    mma16816(acc[mi][ni], &af[mi * 4], &bf[ni * 2]);
        }
    }

    // ------------------------------------------------------------------ epilogue
#pragma unroll
    for (int mi = 0; mi < 2; mi++) {
        const int r0 = bm + wm + mi * 16 + (lane >> 2);
#pragma unroll
        for (int ni = 0; ni < 4; ni++) {
            const int c0 = bn + wn + ni * 8 + (lane & 3) * 2;
            const float b0 = bias[c0], b1 = bias[c0 + 1];
            float v0 = acc[mi][ni][0] + b0;
            float v1 = acc[mi][ni][1] + b1;
            float v2 = acc[mi][ni][2] + b0;
            float v3 = acc[mi][ni][3] + b1;
            if (gelu_flag) {
                v0 = gelu_f(v0); v1 = gelu_f(v1);
                v2 = gelu_f(v2); v3 = gelu_f(v3);
            }
            if (outF) {
                *(float2*)(outF + (size_t)r0 * N + c0)       = make_float2(v0, v1);
                *(float2*)(outF + (size_t)(r0 + 8) * N + c0) = make_float2(v2, v3);
            } else {
                f162 p0; p0.x = __float2half(v0); p0.y = __float2half(v1);
                f162 p1; p1.x = __float2half(v2); p1.y = __float2half(v3);
                *(f162*)(outH + (size_t)r0 * N + c0)       = p0;
                *(f162*)(outH + (size_t)(r0 + 8) * N + c0) = p1;
            }
        }
    }
}

// ----------------------------------------------------------------------------
// fp32 -> fp16 conversion
// ----------------------------------------------------------------------------
__global__ __launch_bounds__(256)
void half_kernel(const float* __restrict__ in, f16* __restrict__ out, int n)
{
    const int i = (blockIdx.x * 256 + threadIdx.x) * 4;
    if (i >= n) return;
    const float4 v = *(const float4*)(in + i);
    f162 p0; p0.x = __float2half(v.x); p0.y = __float2half(v.y);
    f162 p1; p1.x = __float2half(v.z); p1.y = __float2half(v.w);
    uint2 pv;
    pv.x = *(const uint32_t*)&p0; pv.y = *(const uint32_t*)&p1;
    *(uint2*)(out + i) = pv;
}

// ----------------------------------------------------------------------------
// Mask normalization (dtype-robust: bool/uint8, int32, or float32 -> uint8)
// ----------------------------------------------------------------------------
__global__ void mask_norm_kernel(const void* __restrict__ mp)
{
    __shared__ int s_nonbin;
    __shared__ int s_offnz;
    const unsigned char* b = (const unsigned char*)mp;
    if (threadIdx.x == 0) { s_nonbin = 0; s_offnz = 0; }
    __syncthreads();

    int local_nonbin = 0, local_offnz = 0;
    for (int i = threadIdx.x; i < MASK_N; i += blockDim.x) {
        unsigned char v = b[i];
        if (v > 1)                  local_nonbin = 1;
        if ((i & 3) != 0 && v != 0) local_offnz = 1;
    }
    if (local_nonbin) atomicOr(&s_nonbin, 1);
    if (local_offnz)  atomicOr(&s_offnz, 1);
    __syncthreads();

    const int nonbin = s_nonbin, offnz = s_offnz;
    if (nonbin) {
        const float* f = (const float*)mp;
        for (int i = threadIdx.x; i < MASK_N; i += blockDim.x)
            g_mask[i] = (f[i] != 0.0f) ? 1 : 0;
    } else if (offnz) {
        for (int i = threadIdx.x; i < MASK_N; i += blockDim.x)
            g_mask[i] = (b[i] != 0) ? 1 : 0;
    } else {
        const int* ip = (const int*)mp;
        for (int i = threadIdx.x; i < MASK_N; i += blockDim.x)
            g_mask[i] = (ip[i] != 0) ? 1 : 0;
    }
}

// ----------------------------------------------------------------------------
// Attention: one warp per (token, head). Writes CTX as single fp16.
// ----------------------------------------------------------------------------
__global__ __launch_bounds__(256)
void attn_kernel(const float* __restrict__ Q, const float* __restrict__ Kb,
                 const float* __restrict__ Vb, f16* __restrict__ CX)
{
    const int w    = (blockIdx.x * blockDim.x + threadIdx.x) >> 5;
    const int lane = threadIdx.x & 31;
    if (w >= T_TOK * NH) return;
    const int t = w / NH;
    const int h = w % NH;

    const size_t qoff = (size_t)t * HID + h * HD + lane * 2;
    const float2 q = *(const float2*)(Q + qoff);

    float s[NC];
    unsigned allm = 1;
#pragma unroll
    for (int n = 0; n < NC; n++) {
        const float2 kv = *(const float2*)(Kb + ((size_t)t * NC + n) * HID + h * HD + lane * 2);
        float p = q.x * kv.x + q.y * kv.y;
#pragma unroll
        for (int o = 16; o > 0; o >>= 1)
            p += __shfl_xor_sync(0xffffffffu, p, o);
        const unsigned char mn = g_mask[t * NC + n];
        allm &= (mn != 0);
        s[n] = mn ? 1e-10f : p * 0.125f;
    }

    float mx = s[0];
#pragma unroll
    for (int n = 1; n < NC; n++) mx = fmaxf(mx, s[n]);
    float sum = 0.0f;
#pragma unroll
    for (int n = 0; n < NC; n++) { s[n] = expf(s[n] - mx); sum += s[n]; }
    const float inv = 1.0f / sum;

    float2 c = make_float2(0.0f, 0.0f);
#pragma unroll
    for (int n = 0; n < NC; n++) {
        const float2 vv = *(const float2*)(Vb + ((size_t)t * NC + n) * HID + h * HD + lane * 2);
        const float p = s[n] * inv;
        c.x += p * vv.x;
        c.y += p * vv.y;
    }
    if (allm) { c.x = 0.0f; c.y = 0.0f; }

    f162 hp; hp.x = __float2half(c.x); hp.y = __float2half(c.y);
    *(f162*)(CX + qoff) = hp;
}

// ----------------------------------------------------------------------------
// Residual + LayerNorm
// ----------------------------------------------------------------------------
__global__ __launch_bounds__(256)
void ln_kernel(const float* __restrict__ Y, const float* __restrict__ X,
               const float* __restrict__ gamma, const float* __restrict__ beta,
               float* __restrict__ O)
{
    const int t   = blockIdx.x;
    const int tid = threadIdx.x;
    const float* yp = Y + (size_t)t * HID;
    const float* xp = X + (size_t)t * HID;

    float v[3];
    float sum = 0.0f, sq = 0.0f;
#pragma unroll
    for (int i = 0; i < 3; i++) {
        const int idx = tid + i * 256;
        v[i] = yp[idx] + xp[idx];
        sum += v[i];
        sq  += v[i] * v[i];
    }

    const int lane = tid & 31, wid = tid >> 5;
#pragma unroll
    for (int o = 16; o > 0; o >>= 1) {
        sum += __shfl_xor_sync(0xffffffffu, sum, o);
        sq  += __shfl_xor_sync(0xffffffffu, sq,  o);
    }
    __shared__ float rs[8], rq[8];
    if (lane == 0) { rs[wid] = sum; rq[wid] = sq; }
    __syncthreads();
    sum = 0.0f; sq = 0.0f;
#pragma unroll
    for (int i = 0; i < 8; i++) { sum += rs[i]; sq += rq[i]; }

    const float mean = sum * (1.0f / HID);
    const float var  = sq * (1.0f / HID) - mean * mean;
    const float inv  = rsqrtf(var + 1e-12f);

    float* op = O + (size_t)t * HID;
#pragma unroll
    for (int i = 0; i < 3; i++) {
        const int idx = tid + i * 256;
        op[idx] = (v[i] - mean) * inv * gamma[idx] + beta[idx];
    }
}

// ----------------------------------------------------------------------------
// kernel_launch  (launch 5 = K GEMM, the ncu -s 5 -c 1 capture target)
// ----------------------------------------------------------------------------
extern "C" void kernel_launch(void* const* d_in, const int* in_sizes, int n_in,
                              void* d_out, int out_size)
{
    const float* X    = (const float*)d_in[0];
    const float* Cand = (const float*)d_in[1];
    const void*  Mask = d_in[2];
    const float* Wq   = (const float*)d_in[3];
    const float* bq   = (const float*)d_in[4];
    const float* Wk   = (const float*)d_in[5];
    const float* bk   = (const float*)d_in[6];
    const float* Wv   = (const float*)d_in[7];
    const float* bv   = (const float*)d_in[8];
    const float* Wt   = (const float*)d_in[9];
    const float* bt   = (const float*)d_in[10];
    const float* Wc   = (const float*)d_in[11];
    const float* bc   = (const float*)d_in[12];
    const float* gam  = (const float*)d_in[13];
    const float* bet  = (const float*)d_in[14];
    float* out = (float*)d_out;

    void *pQ, *pK, *pV, *pY;
    void *pX16, *pC16, *pCX16, *pH16;
    void *pWq, *pWk, *pWv, *pWt, *pWc;
    cudaGetSymbolAddress(&pQ, g_Q);     cudaGetSymbolAddress(&pK, g_K);
    cudaGetSymbolAddress(&pV, g_V);     cudaGetSymbolAddress(&pY, g_Y);
    cudaGetSymbolAddress(&pX16, g_X16); cudaGetSymbolAddress(&pC16, g_C16);
    cudaGetSymbolAddress(&pCX16, g_CX16); cudaGetSymbolAddress(&pH16, g_H16);
    cudaGetSymbolAddress(&pWq, g_Wq16); cudaGetSymbolAddress(&pWk, g_Wk16);
    cudaGetSymbolAddress(&pWv, g_Wv16); cudaGetSymbolAddress(&pWt, g_Wt16);
    cudaGetSymbolAddress(&pWc, g_Wc16);

    cudaFuncSetAttribute(gemm_f16,
                         cudaFuncAttributeMaxDynamicSharedMemorySize,
                         GEMM_SMEM_TOTAL);

    // launch 0: mask normalization
    mask_norm_kernel<<<1, 1024>>>(Mask);
    // launches 1-4: conversions needed by the K/V GEMMs (+X)
    half_kernel<<<(CAND_M * HID) / 1024, 256>>>(Cand, (f16*)pC16, CAND_M * HID);
    half_kernel<<<(HID * HID) / 1024, 256>>>(Wk, (f16*)pWk, HID * HID);
    half_kernel<<<(HID * HID) / 1024, 256>>>(Wv, (f16*)pWv, HID * HID);
    half_kernel<<<(T_TOK * HID) / 1024, 256>>>(X, (f16*)pX16, T_TOK * HID);

    // launch 5 (ncu target): K = Cand @ Wk^T + bk
    {
        dim3 g(HID / 128, CAND_M / 128);
        gemm_f16<<<g, 512, GEMM_SMEM_TOTAL>>>(
            (const f16*)pC16, (const f16*)pWk, bk,
            (float*)pK, nullptr, CAND_M, HID, HID, 0);
        gemm_f16<<<g, 512, GEMM_SMEM_TOTAL>>>(
            (const f16*)pC16, (const f16*)pWv, bv,
            (float*)pV, nullptr, CAND_M, HID, HID, 0);
    }
    // Q path
    half_kernel<<<(HID * HID) / 1024, 256>>>(Wq, (f16*)pWq, HID * HID);
    {
        dim3 g(HID / 128, T_TOK / 128);
        gemm_f16<<<g, 512, GEMM_SMEM_TOTAL>>>(
            (const f16*)pX16, (const f16*)pWq, bq,
            (float*)pQ, nullptr, T_TOK, HID, HID, 0);
    }
    // attention -> CTX (fp16)
    attn_kernel<<<(T_TOK * NH) / 8, 256>>>((const float*)pQ, (const float*)pK,
                                           (const float*)pV, (f16*)pCX16);
    // H = gelu(CTX @ Wt^T + bt)  (fp16 out)
    half_kernel<<<(FF * HID) / 1024, 256>>>(Wt, (f16*)pWt, FF * HID);
    {
        dim3 g(FF / 128, T_TOK / 128);
        gemm_f16<<<g, 512, GEMM_SMEM_TOTAL>>>(
            (const f16*)pCX16, (const f16*)pWt, bt,
            nullptr, (f16*)pH16, T_TOK, FF, HID, 1);
    }
    // Y = H @ Wc^T + bc
    half_kernel<<<(HID * FF) / 1024, 256>>>(Wc, (f16*)pWc, HID * FF);
    {
        dim3 g(HID / 128, T_TOK / 128);
        gemm_f16<<<g, 512, GEMM_SMEM_TOTAL>>>(
            (const f16*)pH16, (const f16*)pWc, bc,
            (float*)pY, nullptr, T_TOK, HID, FF, 0);
    }
    // out = LayerNorm(Y + X)
    ln_kernel<<<T_TOK, 256>>>((const float*)pY, X, gam, bet, out);
}

// round 15
// speedup vs baseline: 2.4156x; 1.0403x over previous
#include <cuda_runtime.h>
#include <cuda_fp16.h>
#include <cstdint>

// ----------------------------------------------------------------------------
// Problem constants: B=4, S=2048 -> T=8192 tokens, HID=768, NH=12, HD=64,
// NC=8 candidates, FF=3072
// ----------------------------------------------------------------------------
#define T_TOK   8192
#define HID     768
#define NH      12
#define HD      64
#define NC      8
#define FF      3072
#define CAND_M  (T_TOK * NC)   // 65536
#define MASK_N  (T_TOK * NC)   // 65536

typedef __half  f16;
typedef __half2 f162;

// ----------------------------------------------------------------------------
// Scratch (device globals -- no allocation allowed anywhere)
// ----------------------------------------------------------------------------
__device__ float g_Q  [(size_t)T_TOK  * HID];
__device__ float g_Y  [(size_t)T_TOK  * HID];
__device__ unsigned char g_mask[MASK_N];
__device__ int g_mflags[2];   // [0]=nonbin, [1]=offnz. Only ever OR'd with the
                              // same input-derived bits -> idempotent across
                              // graph replays (deterministic output).

// fp16 operands / intermediates
__device__ f16 g_X16 [(size_t)T_TOK  * HID];
__device__ f16 g_C16 [(size_t)CAND_M * HID];
__device__ f16 g_K16 [(size_t)CAND_M * HID];
__device__ f16 g_V16 [(size_t)CAND_M * HID];
__device__ f16 g_CX16[(size_t)T_TOK * HID];
__device__ f16 g_H16 [(size_t)T_TOK * FF];
__device__ f16 g_Wq16[(size_t)HID * HID];
__device__ f16 g_Wk16[(size_t)HID * HID];
__device__ f16 g_Wv16[(size_t)HID * HID];
__device__ f16 g_Wt16[(size_t)FF * HID];
__device__ f16 g_Wc16[(size_t)HID * FF];

// ----------------------------------------------------------------------------
// Helpers
// ----------------------------------------------------------------------------
__device__ __forceinline__ uint32_t smem_to_u32(const void* p) {
    uint32_t a;
    asm("{ .reg .u64 t; cvta.to.shared.u64 t, %1; cvt.u32.u64 %0, t; }"
        : "=r"(a) : "l"(p));
    return a;
}

#define CP_ASYNC16(dst_u32, src_ptr) \
    asm volatile("cp.async.cg.shared.global [%0], [%1], 16;" \
                 :: "r"(dst_u32), "l"(src_ptr) : "memory")
#define CP_COMMIT()  asm volatile("cp.async.commit_group;" ::: "memory")
#define CP_WAIT2()   asm volatile("cp.async.wait_group 2;" ::: "memory")

#define LDSM_X4(r0, r1, r2, r3, addr) \
    asm volatile("ldmatrix.sync.aligned.m8n8.x4.shared.b16 {%0,%1,%2,%3}, [%4];" \
                 : "=r"(r0), "=r"(r1), "=r"(r2), "=r"(r3) : "r"(addr))

// m16n8k16 fp16 MMA with fp32 accumulate (baseline PTX, works at compute_103)
__device__ __forceinline__ void mma16816(float* c, const uint32_t* a, const uint32_t* b)
{
    asm volatile(
        "mma.sync.aligned.m16n8k16.row.col.f32.f16.f16.f32 "
        "{%0,%1,%2,%3}, {%4,%5,%6,%7}, {%8,%9}, {%0,%1,%2,%3};"
        : "+f"(c[0]), "+f"(c[1]), "+f"(c[2]), "+f"(c[3])
        : "r"(a[0]), "r"(a[1]), "r"(a[2]), "r"(a[3]), "r"(b[0]), "r"(b[1]));
}

__device__ __forceinline__ float gelu_f(float x)
{
    return 0.5f * x * (1.0f + erff(x * 0.70710678118654752440f));
}

// ----------------------------------------------------------------------------
// GEMM:  D[M,N] = A[M,K] @ B[N,K]^T + bias[N]   (A,B fp16; fp32 accumulate)
// Single-term fp16 at the mma.sync MMA-count floor (~13 cyc/MMA/SMSP measured
// saturation). CTA tile 128x128, K-chunk 32, 512 threads, warp tile 32x32,
// 4-stage cp.async, ldmatrix.x4, SKP=40 conflict-free.
// ----------------------------------------------------------------------------
#define SKP         40                      // smem row stride in b16 (80 B)
#define MAT_BYTES   (128 * SKP * 2)         // 10240 B per matrix tile
#define STAGE_BYTES (2 * MAT_BYTES)         // A,B = 20480 B
#define NSTAGE      4
#define GEMM_SMEM_TOTAL (NSTAGE * STAGE_BYTES)   // 81920 B

__global__ void __launch_bounds__(512)
gemm_f16(const f16* __restrict__ A, const f16* __restrict__ B,
         const float* __restrict__ bias,
         float* __restrict__ outF, f16* __restrict__ outH,
         int M, int N, int K, int gelu_flag)
{
    extern __shared__ __align__(16) char sm[];
    const uint32_t smem_u32 = smem_to_u32(sm);
    const int tid  = threadIdx.x;
    const int wid  = tid >> 5;
    const int lane = tid & 31;
    const int bm = blockIdx.y * 128;
    const int bn = blockIdx.x * 128;
    const int wm = (wid >> 2) * 32;
    const int wn = (wid & 3) * 32;

    const int lrow = tid >> 2;
    const int lseg = tid & 3;

    const int aRow = (lane & 7) + ((lane >> 3) & 1) * 8;
    const int aCol = (lane >> 4) * 8;
    const uint32_t relA0 = (uint32_t)((wm +  0 + aRow) * SKP * 2 + aCol * 2);
    const uint32_t relA1 = (uint32_t)((wm + 16 + aRow) * SKP * 2 + aCol * 2);
    const int bRow = (lane & 7) + (lane >> 4) * 8;
    const int bCol = ((lane >> 3) & 1) * 8;
    const uint32_t relB0 = (uint32_t)((wn +  0 + bRow) * SKP * 2 + bCol * 2);
    const uint32_t relB1 = (uint32_t)((wn + 16 + bRow) * SKP * 2 + bCol * 2);

    float acc[2][4][4];
#pragma unroll
    for (int i = 0; i < 2; i++)
#pragma unroll
        for (int j = 0; j < 4; j++)
#pragma unroll
            for (int r = 0; r < 4; r++) acc[i][j][r] = 0.0f;

    auto prefetch = [&](int k0, int s) {
        const uint32_t sb = smem_u32 + s * STAGE_BYTES;
        const uint32_t so = (uint32_t)(lrow * (SKP * 2) + lseg * 16);
        const size_t ga = (size_t)(bm + lrow) * K + k0 + lseg * 8;
        const size_t gb = (size_t)(bn + lrow) * K + k0 + lseg * 8;
        CP_ASYNC16(sb + so, A + ga);
        CP_ASYNC16(sb + MAT_BYTES + so, B + gb);
    };

    const int nchunks = K >> 5;

#pragma unroll
    for (int p = 0; p < NSTAGE - 1; p++) {
        if (p < nchunks) prefetch(p << 5, p);
        CP_COMMIT();
    }

    for (int c = 0; c < nchunks; c++) {
        CP_WAIT2();
        __syncthreads();
        if (c + NSTAGE - 1 < nchunks)
            prefetch((c + NSTAGE - 1) << 5, (c + NSTAGE - 1) & (NSTAGE - 1));
        CP_COMMIT();

        const uint32_t st = smem_u32 + (c & (NSTAGE - 1)) * STAGE_BYTES;

#pragma unroll
        for (int kk = 0; kk < 32; kk += 16) {
            const uint32_t kb = st + kk * 2;
            uint32_t af[8], bf[8];

            LDSM_X4(af[0], af[1], af[2], af[3], kb + relA0);
            LDSM_X4(af[4], af[5], af[6], af[7], kb + relA1);
            LDSM_X4(bf[0], bf[1], bf[2], bf[3], kb + MAT_BYTES + relB0);
            LDSM_X4(bf[4], bf[5], bf[6], bf[7], kb + MAT_BYTES + relB1);

#pragma unroll
            for (int mi = 0; mi < 2; mi++)
#pragma unroll
                for (int ni = 0; ni < 4; ni++)
                    mma16816(acc[mi][ni], &af[mi * 4], &bf[ni * 2]);
        }
    }

    // epilogue
#pragma unroll
    for (int mi = 0; mi < 2; mi++) {
        const int r0 = bm + wm + mi * 16 + (lane >> 2);
#pragma unroll
        for (int ni = 0; ni < 4; ni++) {
            const int c0 = bn + wn + ni * 8 + (lane & 3) * 2;
            const float b0 = bias[c0], b1 = bias[c0 + 1];
            float v0 = acc[mi][ni][0] + b0;
            float v1 = acc[mi][ni][1] + b1;
            float v2 = acc[mi][ni][2] + b0;
            float v3 = acc[mi][ni][3] + b1;
            if (gelu_flag) {
                v0 = gelu_f(v0); v1 = gelu_f(v1);
                v2 = gelu_f(v2); v3 = gelu_f(v3);
            }
            if (outF) {
                *(float2*)(outF + (size_t)r0 * N + c0)       = make_float2(v0, v1);
                *(float2*)(outF + (size_t)(r0 + 8) * N + c0) = make_float2(v2, v3);
            } else {
                f162 p0; p0.x = __float2half(v0); p0.y = __float2half(v1);
                f162 p1; p1.x = __float2half(v2); p1.y = __float2half(v3);
                *(f162*)(outH + (size_t)r0 * N + c0)       = p0;
                *(f162*)(outH + (size_t)(r0 + 8) * N + c0) = p1;
            }
        }
    }
}

// ----------------------------------------------------------------------------
// fp32 -> fp16 conversion
// ----------------------------------------------------------------------------
__global__ __launch_bounds__(256)
void half_kernel(const float* __restrict__ in, f16* __restrict__ out, int n)
{
    const int i = (blockIdx.x * 256 + threadIdx.x) * 4;
    if (i >= n) return;
    const float4 v = *(const float4*)(in + i);
    f162 p0; p0.x = __float2half(v.x); p0.y = __float2half(v.y);
    f162 p1; p1.x = __float2half(v.z); p1.y = __float2half(v.w);
    uint2 pv;
    pv.x = *(const uint32_t*)&p0; pv.y = *(const uint32_t*)&p1;
    *(uint2*)(out + i) = pv;
}

// ----------------------------------------------------------------------------
// Mask dtype detection (parallel). Flags only ever transition 0->1 driven by
// the (fixed) input bytes, so repeated graph replays are idempotent.
// ----------------------------------------------------------------------------
__global__ __launch_bounds__(256)
void mask_detect_kernel(const void* __restrict__ mp)
{
    const unsigned char* b = (const unsigned char*)mp;
    int local_nonbin = 0, local_offnz = 0;
    for (int i = blockIdx.x * 256 + threadIdx.x; i < MASK_N; i += gridDim.x * 256) {
        unsigned char v = b[i];
        if (v > 1)                  local_nonbin = 1;
        if ((i & 3) != 0 && v != 0) local_offnz = 1;
    }
    if (local_nonbin) atomicOr(&g_mflags[0], 1);
    if (local_offnz)  atomicOr(&g_mflags[1], 1);
}

__global__ __launch_bounds__(256)
void mask_convert_kernel(const void* __restrict__ mp)
{
    const int nonbin = g_mflags[0], offnz = g_mflags[1];
    const int i0 = blockIdx.x * 256 + threadIdx.x;
    const int stride = gridDim.x * 256;
    if (nonbin) {
        const float* f = (const float*)mp;
        for (int i = i0; i < MASK_N; i += stride)
            g_mask[i] = (f[i] != 0.0f) ? 1 : 0;
    } else if (offnz) {
        const unsigned char* b = (const unsigned char*)mp;
        for (int i = i0; i < MASK_N; i += stride)
            g_mask[i] = (b[i] != 0) ? 1 : 0;
    } else {
        const int* ip = (const int*)mp;
        for (int i = i0; i < MASK_N; i += stride)
            g_mask[i] = (ip[i] != 0) ? 1 : 0;
    }
}

// ----------------------------------------------------------------------------
// Attention: one warp per (token, head). Q fp32; K,V fp16 (written by the
// K/V GEMM epilogues). Writes CTX as fp16.
// ----------------------------------------------------------------------------
__global__ __launch_bounds__(256)
void attn_kernel(const float* __restrict__ Q, const f16* __restrict__ Kb,
                 const f16* __restrict__ Vb, f16* __restrict__ CX)
{
    const int w    = (blockIdx.x * blockDim.x + threadIdx.x) >> 5;
    const int lane = threadIdx.x & 31;
    if (w >= T_TOK * NH) return;
    const int t = w / NH;
    const int h = w % NH;

    const size_t qoff = (size_t)t * HID + h * HD + lane * 2;
    const float2 q = *(const float2*)(Q + qoff);

    float s[NC];
    unsigned allm = 1;
#pragma unroll
    for (int n = 0; n < NC; n++) {
        const f162 kv = *(const f162*)(Kb + ((size_t)t * NC + n) * HID + h * HD + lane * 2);
        float p = q.x * __half2float(kv.x) + q.y * __half2float(kv.y);
#pragma unroll
        for (int o = 16; o > 0; o >>= 1)
            p += __shfl_xor_sync(0xffffffffu, p, o);
        const unsigned char mn = g_mask[t * NC + n];
        allm &= (mn != 0);
        s[n] = mn ? 1e-10f : p * 0.125f;
    }

    float mx = s[0];
#pragma unroll
    for (int n = 1; n < NC; n++) mx = fmaxf(mx, s[n]);
    float sum = 0.0f;
#pragma unroll
    for (int n = 0; n < NC; n++) { s[n] = expf(s[n] - mx); sum += s[n]; }
    const float inv = 1.0f / sum;

    float2 c = make_float2(0.0f, 0.0f);
#pragma unroll
    for (int n = 0; n < NC; n++) {
        const f162 vv = *(const f162*)(Vb + ((size_t)t * NC + n) * HID + h * HD + lane * 2);
        const float p = s[n] * inv;
        c.x += p * __half2float(vv.x);
        c.y += p * __half2float(vv.y);
    }
    if (allm) { c.x = 0.0f; c.y = 0.0f; }

    f162 hp; hp.x = __float2half(c.x); hp.y = __float2half(c.y);
    *(f162*)(CX + qoff) = hp;
}

// ----------------------------------------------------------------------------
// Residual + LayerNorm
// ----------------------------------------------------------------------------
__global__ __launch_bounds__(256)
void ln_kernel(const float* __restrict__ Y, const float* __restrict__ X,
               const float* __restrict__ gamma, const float* __restrict__ beta,
               float* __restrict__ O)
{
    const int t   = blockIdx.x;
    const int tid = threadIdx.x;
    const float* yp = Y + (size_t)t * HID;
    const float* xp = X + (size_t)t * HID;

    float v[3];
    float sum = 0.0f, sq = 0.0f;
#pragma unroll
    for (int i = 0; i < 3; i++) {
        const int idx = tid + i * 256;
        v[i] = yp[idx] + xp[idx];
        sum += v[i];
        sq  += v[i] * v[i];
    }

    const int lane = tid & 31, wid = tid >> 5;
#pragma unroll
    for (int o = 16; o > 0; o >>= 1) {
        sum += __shfl_xor_sync(0xffffffffu, sum, o);
        sq  += __shfl_xor_sync(0xffffffffu, sq,  o);
    }
    __shared__ float rs[8], rq[8];
    if (lane == 0) { rs[wid] = sum; rq[wid] = sq; }
    __syncthreads();
    sum = 0.0f; sq = 0.0f;
#pragma unroll
    for (int i = 0; i < 8; i++) { sum += rs[i]; sq += rq[i]; }

    const float mean = sum * (1.0f / HID);
    const float var  = sq * (1.0f / HID) - mean * mean;
    const float inv  = rsqrtf(var + 1e-12f);

    float* op = O + (size_t)t * HID;
#pragma unroll
    for (int i = 0; i < 3; i++) {
        const int idx = tid + i * 256;
        op[idx] = (v[i] - mean) * inv * gamma[idx] + beta[idx];
    }
}

// ----------------------------------------------------------------------------
// kernel_launch  (launch index 5 = K GEMM, the ncu -s 5 -c 1 capture target)
// ----------------------------------------------------------------------------
extern "C" void kernel_launch(void* const* d_in, const int* in_sizes, int n_in,
                              void* d_out, int out_size)
{
    const float* X    = (const float*)d_in[0];
    const float* Cand = (const float*)d_in[1];
    const void*  Mask = d_in[2];
    const float* Wq   = (const float*)d_in[3];
    const float* bq   = (const float*)d_in[4];
    const float* Wk   = (const float*)d_in[5];
    const float* bk   = (const float*)d_in[6];
    const float* Wv   = (const float*)d_in[7];
    const float* bv   = (const float*)d_in[8];
    const float* Wt   = (const float*)d_in[9];
    const float* bt   = (const float*)d_in[10];
    const float* Wc   = (const float*)d_in[11];
    const float* bc   = (const float*)d_in[12];
    const float* gam  = (const float*)d_in[13];
    const float* bet  = (const float*)d_in[14];
    float* out = (float*)d_out;

    void *pQ, *pY;
    void *pX16, *pC16, *pK16, *pV16, *pCX16, *pH16;
    void *pWq, *pWk, *pWv, *pWt, *pWc;
    cudaGetSymbolAddress(&pQ, g_Q);       cudaGetSymbolAddress(&pY, g_Y);
    cudaGetSymbolAddress(&pX16, g_X16);   cudaGetSymbolAddress(&pC16, g_C16);
    cudaGetSymbolAddress(&pK16, g_K16);   cudaGetSymbolAddress(&pV16, g_V16);
    cudaGetSymbolAddress(&pCX16, g_CX16); cudaGetSymbolAddress(&pH16, g_H16);
    cudaGetSymbolAddress(&pWq, g_Wq16);   cudaGetSymbolAddress(&pWk, g_Wk16);
    cudaGetSymbolAddress(&pWv, g_Wv16);   cudaGetSymbolAddress(&pWt, g_Wt16);
    cudaGetSymbolAddress(&pWc, g_Wc16);

    cudaFuncSetAttribute(gemm_f16,
                         cudaFuncAttributeMaxDynamicSharedMemorySize,
                         GEMM_SMEM_TOTAL);

    // launches 0-1: mask dtype detect + convert (parallel)
    mask_detect_kernel<<<64, 256>>>(Mask);
    mask_convert_kernel<<<64, 256>>>(Mask);
    // launches 2-4: conversions needed by the K/V GEMMs
    half_kernel<<<(CAND_M * HID) / 1024, 256>>>(Cand, (f16*)pC16, CAND_M * HID);
    half_kernel<<<(HID * HID) / 1024, 256>>>(Wk, (f16*)pWk, HID * HID);
    half_kernel<<<(HID * HID) / 1024, 256>>>(Wv, (f16*)pWv, HID * HID);

    // launch 5 (ncu target): K = Cand @ Wk^T + bk  (fp16 out)
    {
        dim3 g(HID / 128, CAND_M / 128);
        gemm_f16<<<g, 512, GEMM_SMEM_TOTAL>>>(
            (const f16*)pC16, (const f16*)pWk, bk,
            nullptr, (f16*)pK16, CAND_M, HID, HID, 0);
        gemm_f16<<<g, 512, GEMM_SMEM_TOTAL>>>(
            (const f16*)pC16, (const f16*)pWv, bv,
            nullptr, (f16*)pV16, CAND_M, HID, HID, 0);
    }
    // Q path (fp32 out)
    half_kernel<<<(T_TOK * HID) / 1024, 256>>>(X, (f16*)pX16, T_TOK * HID);
    half_kernel<<<(HID * HID) / 1024, 256>>>(Wq, (f16*)pWq, HID * HID);
    {
        dim3 g(HID / 128, T_TOK / 128);
        gemm_f16<<<g, 512, GEMM_SMEM_TOTAL>>>(
            (const f16*)pX16, (const f16*)pWq, bq,
            (float*)pQ, nullptr, T_TOK, HID, HID, 0);
    }
    // attention -> CTX (fp16), K/V read as fp16
    attn_kernel<<<(T_TOK * NH) / 8, 256>>>((const float*)pQ, (const f16*)pK16,
                                           (const f16*)pV16, (f16*)pCX16);
    // H = gelu(CTX @ Wt^T + bt)  (fp16 out)
    half_kernel<<<(FF * HID) / 1024, 256>>>(Wt, (f16*)pWt, FF * HID);
    {
        dim3 g(FF / 128, T_TOK / 128);
        gemm_f16<<<g, 512, GEMM_SMEM_TOTAL>>>(
            (const f16*)pCX16, (const f16*)pWt, bt,
            nullptr, (f16*)pH16, T_TOK, FF, HID, 1);
    }
    // Y = H @ Wc^T + bc  (fp32 out)
    half_kernel<<<(HID * FF) / 1024, 256>>>(Wc, (f16*)pWc, HID * FF);
    {
        dim3 g(HID / 128, T_TOK / 128);
        gemm_f16<<<g, 512, GEMM_SMEM_TOTAL>>>(
            (const f16*)pH16, (const f16*)pWc, bc,
            (float*)pY, nullptr, T_TOK, HID, FF, 0);
    }
    // out = LayerNorm(Y + X)
    ln_kernel<<<T_TOK, 256>>>((const float*)pY, X, gam, bet, out);
}

// round 16
// speedup vs baseline: 2.5114x; 1.0396x over previous
#include <cuda_runtime.h>
#include <cuda_fp16.h>
#include <cstdint>

// ----------------------------------------------------------------------------
// Problem constants: B=4, S=2048 -> T=8192 tokens, HID=768, NH=12, HD=64,
// NC=8 candidates, FF=3072
// ----------------------------------------------------------------------------
#define T_TOK   8192
#define HID     768
#define NH      12
#define HD      64
#define NC      8
#define FF      3072
#define CAND_M  (T_TOK * NC)   // 65536
#define MASK_N  (T_TOK * NC)   // 65536

typedef __half  f16;
typedef __half2 f162;

// ----------------------------------------------------------------------------
// Scratch (device globals -- no allocation allowed anywhere)
// ----------------------------------------------------------------------------
__device__ float g_Y  [(size_t)T_TOK  * HID];
__device__ unsigned char g_mask[MASK_N];
__device__ int g_mflags[2];   // 0->1 transitions driven only by fixed input
                              // bytes -> idempotent across graph replays.

__device__ f16 g_X16 [(size_t)T_TOK  * HID];
__device__ f16 g_C16 [(size_t)CAND_M * HID];
__device__ f16 g_Q16 [(size_t)T_TOK  * HID];
__device__ f16 g_K16 [(size_t)CAND_M * HID];
__device__ f16 g_V16 [(size_t)CAND_M * HID];
__device__ f16 g_CX16[(size_t)T_TOK * HID];
__device__ f16 g_H16 [(size_t)T_TOK * FF];
__device__ f16 g_Wq16[(size_t)HID * HID];
__device__ f16 g_Wk16[(size_t)HID * HID];
__device__ f16 g_Wv16[(size_t)HID * HID];
__device__ f16 g_Wt16[(size_t)FF * HID];
__device__ f16 g_Wc16[(size_t)HID * FF];

// ----------------------------------------------------------------------------
// Helpers
// ----------------------------------------------------------------------------
__device__ __forceinline__ uint32_t smem_to_u32(const void* p) {
    uint32_t a;
    asm("{ .reg .u64 t; cvta.to.shared.u64 t, %1; cvt.u32.u64 %0, t; }"
        : "=r"(a) : "l"(p));
    return a;
}

#define CP_ASYNC16(dst_u32, src_ptr) \
    asm volatile("cp.async.cg.shared.global [%0], [%1], 16;" \
                 :: "r"(dst_u32), "l"(src_ptr) : "memory")
#define CP_COMMIT()  asm volatile("cp.async.commit_group;" ::: "memory")
#define CP_WAIT2()   asm volatile("cp.async.wait_group 2;" ::: "memory")

#define LDSM_X4(r0, r1, r2, r3, addr) \
    asm volatile("ldmatrix.sync.aligned.m8n8.x4.shared.b16 {%0,%1,%2,%3}, [%4];" \
                 : "=r"(r0), "=r"(r1), "=r"(r2), "=r"(r3) : "r"(addr))

__device__ __forceinline__ void mma16816(float* c, const uint32_t* a, const uint32_t* b)
{
    asm volatile(
        "mma.sync.aligned.m16n8k16.row.col.f32.f16.f16.f32 "
        "{%0,%1,%2,%3}, {%4,%5,%6,%7}, {%8,%9}, {%0,%1,%2,%3};"
        : "+f"(c[0]), "+f"(c[1]), "+f"(c[2]), "+f"(c[3])
        : "r"(a[0]), "r"(a[1]), "r"(a[2]), "r"(a[3]), "r"(b[0]), "r"(b[1]));
}

__device__ __forceinline__ float gelu_f(float x)
{
    return 0.5f * x * (1.0f + erff(x * 0.70710678118654752440f));
}

// ----------------------------------------------------------------------------
// Shared GEMM tiling constants (validated Rounds 9-14):
// CTA 128x128, K-chunk 32, 512 threads, warp tile 32x32, 4-stage cp.async,
// ldmatrix.x4, SKP=40 conflict-free padding. fp16 single-term is the
// MMA-count floor on the fallback-HMMA pipe (~13 cyc/MMA/SMSP saturation).
// ----------------------------------------------------------------------------
#define SKP         40
#define MAT_BYTES   (128 * SKP * 2)         // 10240 B
#define STAGE_BYTES (2 * MAT_BYTES)         // 20480 B
#define NSTAGE      4
#define GEMM_SMEM_TOTAL (NSTAGE * STAGE_BYTES)   // 81920 B

// Core mainloop + epilogue as a device function (shared by both kernels).
__device__ __forceinline__ void gemm_body(
    char* sm, const f16* __restrict__ A, const f16* __restrict__ B,
    const float* __restrict__ bias,
    float* __restrict__ outF, f16* __restrict__ outH,
    int N, int K, int bm, int bn, int gelu_flag)
{
    const uint32_t smem_u32 = smem_to_u32(sm);
    const int tid  = threadIdx.x;
    const int wid  = tid >> 5;
    const int lane = tid & 31;
    const int wm = (wid >> 2) * 32;
    const int wn = (wid & 3) * 32;

    const int lrow = tid >> 2;
    const int lseg = tid & 3;

    const int aRow = (lane & 7) + ((lane >> 3) & 1) * 8;
    const int aCol = (lane >> 4) * 8;
    const uint32_t relA0 = (uint32_t)((wm +  0 + aRow) * SKP * 2 + aCol * 2);
    const uint32_t relA1 = (uint32_t)((wm + 16 + aRow) * SKP * 2 + aCol * 2);
    const int bRow = (lane & 7) + (lane >> 4) * 8;
    const int bCol = ((lane >> 3) & 1) * 8;
    const uint32_t relB0 = (uint32_t)((wn +  0 + bRow) * SKP * 2 + bCol * 2);
    const uint32_t relB1 = (uint32_t)((wn + 16 + bRow) * SKP * 2 + bCol * 2);

    float acc[2][4][4];
#pragma unroll
    for (int i = 0; i < 2; i++)
#pragma unroll
        for (int j = 0; j < 4; j++)
#pragma unroll
            for (int r = 0; r < 4; r++) acc[i][j][r] = 0.0f;

    auto prefetch = [&](int k0, int s) {
        const uint32_t sb = smem_u32 + s * STAGE_BYTES;
        const uint32_t so = (uint32_t)(lrow * (SKP * 2) + lseg * 16);
        const size_t ga = (size_t)(bm + lrow) * K + k0 + lseg * 8;
        const size_t gb = (size_t)(bn + lrow) * K + k0 + lseg * 8;
        CP_ASYNC16(sb + so, A + ga);
        CP_ASYNC16(sb + MAT_BYTES + so, B + gb);
    };

    const int nchunks = K >> 5;

#pragma unroll
    for (int p = 0; p < NSTAGE - 1; p++) {
        if (p < nchunks) prefetch(p << 5, p);
        CP_COMMIT();
    }

    for (int c = 0; c < nchunks; c++) {
        CP_WAIT2();
        __syncthreads();
        if (c + NSTAGE - 1 < nchunks)
            prefetch((c + NSTAGE - 1) << 5, (c + NSTAGE - 1) & (NSTAGE - 1));
        CP_COMMIT();

        const uint32_t st = smem_u32 + (c & (NSTAGE - 1)) * STAGE_BYTES;

#pragma unroll
        for (int kk = 0; kk < 32; kk += 16) {
            const uint32_t kb = st + kk * 2;
            uint32_t af[8], bf[8];

            LDSM_X4(af[0], af[1], af[2], af[3], kb + relA0);
            LDSM_X4(af[4], af[5], af[6], af[7], kb + relA1);
            LDSM_X4(bf[0], bf[1], bf[2], bf[3], kb + MAT_BYTES + relB0);
            LDSM_X4(bf[4], bf[5], bf[6], bf[7], kb + MAT_BYTES + relB1);

#pragma unroll
            for (int mi = 0; mi < 2; mi++)
#pragma unroll
                for (int ni = 0; ni < 4; ni++)
                    mma16816(acc[mi][ni], &af[mi * 4], &bf[ni * 2]);
        }
    }

    // epilogue
#pragma unroll
    for (int mi = 0; mi < 2; mi++) {
        const int r0 = bm + wm + mi * 16 + (lane >> 2);
#pragma unroll
        for (int ni = 0; ni < 4; ni++) {
            const int c0 = bn + wn + ni * 8 + (lane & 3) * 2;
            const float b0 = bias[c0], b1 = bias[c0 + 1];
            float v0 = acc[mi][ni][0] + b0;
            float v1 = acc[mi][ni][1] + b1;
            float v2 = acc[mi][ni][2] + b0;
            float v3 = acc[mi][ni][3] + b1;
            if (gelu_flag) {
                v0 = gelu_f(v0); v1 = gelu_f(v1);
                v2 = gelu_f(v2); v3 = gelu_f(v3);
            }
            if (outF) {
                *(float2*)(outF + (size_t)r0 * N + c0)       = make_float2(v0, v1);
                *(float2*)(outF + (size_t)(r0 + 8) * N + c0) = make_float2(v2, v3);
            } else {
                f162 p0; p0.x = __float2half(v0); p0.y = __float2half(v1);
                f162 p1; p1.x = __float2half(v2); p1.y = __float2half(v3);
                *(f162*)(outH + (size_t)r0 * N + c0)       = p0;
                *(f162*)(outH + (size_t)(r0 + 8) * N + c0) = p1;
            }
        }
    }
}

// Generic GEMM (H and Y stages)
__global__ void __launch_bounds__(512)
gemm_f16(const f16* __restrict__ A, const f16* __restrict__ B,
         const float* __restrict__ bias,
         float* __restrict__ outF, f16* __restrict__ outH,
         int M, int N, int K, int gelu_flag)
{
    extern __shared__ __align__(16) char sm[];
    gemm_body(sm, A, B, bias, outF, outH, N, K,
              blockIdx.y * 128, blockIdx.x * 128, gelu_flag);
}

// Fused Q/K/V GEMM: blockIdx.z selects the problem. z=0: K, z=1: V (M=65536),
// z=2: Q (M=8192; y>=64 exits). All share N=K=768, fp16 out, no gelu.
// Pools three launches' wave tails into one 44-wave launch.
__global__ void __launch_bounds__(512)
gemm_qkv(const f16* __restrict__ C16, const f16* __restrict__ X16,
         const f16* __restrict__ Wk, const f16* __restrict__ Wv,
         const f16* __restrict__ Wq,
         const float* __restrict__ bk, const float* __restrict__ bv,
         const float* __restrict__ bq,
         f16* __restrict__ K16, f16* __restrict__ V16, f16* __restrict__ Q16)
{
    extern __shared__ __align__(16) char sm[];
    const int z = blockIdx.z;
    if (z == 2 && blockIdx.y >= (T_TOK / 128)) return;
    const f16* A = (z == 2) ? X16 : C16;
    const f16* B = (z == 0) ? Wk : (z == 1) ? Wv : Wq;
    const float* bias = (z == 0) ? bk : (z == 1) ? bv : bq;
    f16* out = (z == 0) ? K16 : (z == 1) ? V16 : Q16;
    gemm_body(sm, A, B, bias, nullptr, out, HID, HID,
              blockIdx.y * 128, blockIdx.x * 128, 0);
}

// ----------------------------------------------------------------------------
// Mega-convert: all fp32->fp16 conversions in ONE grid-strided kernel.
// Segment table in float4 units (compile-time).
// ----------------------------------------------------------------------------
#define SEG_C   (CAND_M * HID / 4)                 // 12582912
#define SEG_X   (T_TOK * HID / 4)                  //  1572864
#define SEG_W   (HID * HID / 4)                    //   147456
#define SEG_T   (FF * HID / 4)                     //   589824
#define CUM0    SEG_C
#define CUM1    (CUM0 + SEG_X)
#define CUM2    (CUM1 + SEG_W)
#define CUM3    (CUM2 + SEG_W)
#define CUM4    (CUM3 + SEG_W)
#define CUM5    (CUM4 + SEG_T)
#define CUM6    (CUM5 + SEG_T)                     // total float4s

__global__ __launch_bounds__(256)
void convert_all_kernel(const float* __restrict__ Cand, const float* __restrict__ X,
                        const float* __restrict__ Wq, const float* __restrict__ Wk,
                        const float* __restrict__ Wv, const float* __restrict__ Wt,
                        const float* __restrict__ Wc,
                        f16* __restrict__ C16, f16* __restrict__ X16,
                        f16* __restrict__ Wq16, f16* __restrict__ Wk16,
                        f16* __restrict__ Wv16, f16* __restrict__ Wt16,
                        f16* __restrict__ Wc16)
{
    for (int i = blockIdx.x * 256 + threadIdx.x; i < CUM6; i += gridDim.x * 256) {
        const float* src;
        f16* dst;
        int off;
        if      (i < CUM0) { src = Cand; dst = C16;  off = i; }
        else if (i < CUM1) { src = X;    dst = X16;  off = i - CUM0; }
        else if (i < CUM2) { src = Wq;   dst = Wq16; off = i - CUM1; }
        else if (i < CUM3) { src = Wk;   dst = Wk16; off = i - CUM2; }
        else if (i < CUM4) { src = Wv;   dst = Wv16; off = i - CUM3; }
        else if (i < CUM5) { src = Wt;   dst = Wt16; off = i - CUM4; }
        else               { src = Wc;   dst = Wc16; off = i - CUM5; }
        const float4 v = *(const float4*)(src + (size_t)off * 4);
        f162 p0; p0.x = __float2half(v.x); p0.y = __float2half(v.y);
        f162 p1; p1.x = __float2half(v.z); p1.y = __float2half(v.w);
        uint2 pv;
        pv.x = *(const uint32_t*)&p0; pv.y = *(const uint32_t*)&p1;
        *(uint2*)(dst + (size_t)off * 4) = pv;
    }
}

// ----------------------------------------------------------------------------
// Mask dtype detect + convert (parallel, idempotent flags)
// ----------------------------------------------------------------------------
__global__ __launch_bounds__(256)
void mask_detect_kernel(const void* __restrict__ mp)
{
    const unsigned char* b = (const unsigned char*)mp;
    int local_nonbin = 0, local_offnz = 0;
    for (int i = blockIdx.x * 256 + threadIdx.x; i < MASK_N; i += gridDim.x * 256) {
        unsigned char v = b[i];
        if (v > 1)                  local_nonbin = 1;
        if ((i & 3) != 0 && v != 0) local_offnz = 1;
    }
    if (local_nonbin) atomicOr(&g_mflags[0], 1);
    if (local_offnz)  atomicOr(&g_mflags[1], 1);
}

__global__ __launch_bounds__(256)
void mask_convert_kernel(const void* __restrict__ mp)
{
    const int nonbin = g_mflags[0], offnz = g_mflags[1];
    const int i0 = blockIdx.x * 256 + threadIdx.x;
    const int stride = gridDim.x * 256;
    if (nonbin) {
        const float* f = (const float*)mp;
        for (int i = i0; i < MASK_N; i += stride)
            g_mask[i] = (f[i] != 0.0f) ? 1 : 0;
    } else if (offnz) {
        const unsigned char* b = (const unsigned char*)mp;
        for (int i = i0; i < MASK_N; i += stride)
            g_mask[i] = (b[i] != 0) ? 1 : 0;
    } else {
        const int* ip = (const int*)mp;
        for (int i = i0; i < MASK_N; i += stride)
            g_mask[i] = (ip[i] != 0) ? 1 : 0;
    }
}

// ----------------------------------------------------------------------------
// Attention: one warp per (token, head). Q, K, V all fp16; CTX fp16 out.
// ----------------------------------------------------------------------------
__global__ __launch_bounds__(256)
void attn_kernel(const f16* __restrict__ Qb, const f16* __restrict__ Kb,
                 const f16* __restrict__ Vb, f16* __restrict__ CX)
{
    const int w    = (blockIdx.x * blockDim.x + threadIdx.x) >> 5;
    const int lane = threadIdx.x & 31;
    if (w >= T_TOK * NH) return;
    const int t = w / NH;
    const int h = w % NH;

    const size_t qoff = (size_t)t * HID + h * HD + lane * 2;
    const f162 qh = *(const f162*)(Qb + qoff);
    const float qx = __half2float(qh.x), qy = __half2float(qh.y);

    float s[NC];
    unsigned allm = 1;
#pragma unroll
    for (int n = 0; n < NC; n++) {
        const f162 kv = *(const f162*)(Kb + ((size_t)t * NC + n) * HID + h * HD + lane * 2);
        float p = qx * __half2float(kv.x) + qy * __half2float(kv.y);
#pragma unroll
        for (int o = 16; o > 0; o >>= 1)
            p += __shfl_xor_sync(0xffffffffu, p, o);
        const unsigned char mn = g_mask[t * NC + n];
        allm &= (mn != 0);
        s[n] = mn ? 1e-10f : p * 0.125f;
    }

    float mx = s[0];
#pragma unroll
    for (int n = 1; n < NC; n++) mx = fmaxf(mx, s[n]);
    float sum = 0.0f;
#pragma unroll
    for (int n = 0; n < NC; n++) { s[n] = expf(s[n] - mx); sum += s[n]; }
    const float inv = 1.0f / sum;

    float2 c = make_float2(0.0f, 0.0f);
#pragma unroll
    for (int n = 0; n < NC; n++) {
        const f162 vv = *(const f162*)(Vb + ((size_t)t * NC + n) * HID + h * HD + lane * 2);
        const float p = s[n] * inv;
        c.x += p * __half2float(vv.x);
        c.y += p * __half2float(vv.y);
    }
    if (allm) { c.x = 0.0f; c.y = 0.0f; }

    f162 hp; hp.x = __float2half(c.x); hp.y = __float2half(c.y);
    *(f162*)(CX + qoff) = hp;
}

// ----------------------------------------------------------------------------
// Residual + LayerNorm
// ----------------------------------------------------------------------------
__global__ __launch_bounds__(256)
void ln_kernel(const float* __restrict__ Y, const float* __restrict__ X,
               const float* __restrict__ gamma, const float* __restrict__ beta,
               float* __restrict__ O)
{
    const int t   = blockIdx.x;
    const int tid = threadIdx.x;
    const float* yp = Y + (size_t)t * HID;
    const float* xp = X + (size_t)t * HID;

    float v[3];
    float sum = 0.0f, sq = 0.0f;
#pragma unroll
    for (int i = 0; i < 3; i++) {
        const int idx = tid + i * 256;
        v[i] = yp[idx] + xp[idx];
        sum += v[i];
        sq  += v[i] * v[i];
    }

    const int lane = tid & 31, wid = tid >> 5;
#pragma unroll
    for (int o = 16; o > 0; o >>= 1) {
        sum += __shfl_xor_sync(0xffffffffu, sum, o);
        sq  += __shfl_xor_sync(0xffffffffu, sq,  o);
    }
    __shared__ float rs[8], rq[8];
    if (lane == 0) { rs[wid] = sum; rq[wid] = sq; }
    __syncthreads();
    sum = 0.0f; sq = 0.0f;
#pragma unroll
    for (int i = 0; i < 8; i++) { sum += rs[i]; sq += rq[i]; }

    const float mean = sum * (1.0f / HID);
    const float var  = sq * (1.0f / HID) - mean * mean;
    const float inv  = rsqrtf(var + 1e-12f);

    float* op = O + (size_t)t * HID;
#pragma unroll
    for (int i = 0; i < 3; i++) {
        const int idx = tid + i * 256;
        op[idx] = (v[i] - mean) * inv * gamma[idx] + beta[idx];
    }
}

// ----------------------------------------------------------------------------
// kernel_launch — 8 launches total
//   0 mask_detect, 1 mask_convert, 2 convert_all, 3 gemm_qkv(z=3),
//   4 attn, 5 H GEMM (ncu -s 5 target), 6 Y GEMM, 7 LN
// ----------------------------------------------------------------------------
extern "C" void kernel_launch(void* const* d_in, const int* in_sizes, int n_in,
                              void* d_out, int out_size)
{
    const float* X    = (const float*)d_in[0];
    const float* Cand = (const float*)d_in[1];
    const void*  Mask = d_in[2];
    const float* Wq   = (const float*)d_in[3];
    const float* bq   = (const float*)d_in[4];
    const float* Wk   = (const float*)d_in[5];
    const float* bk   = (const float*)d_in[6];
    const float* Wv   = (const float*)d_in[7];
    const float* bv   = (const float*)d_in[8];
    const float* Wt   = (const float*)d_in[9];
    const float* bt   = (const float*)d_in[10];
    const float* Wc   = (const float*)d_in[11];
    const float* bc   = (const float*)d_in[12];
    const float* gam  = (const float*)d_in[13];
    const float* bet  = (const float*)d_in[14];
    float* out = (float*)d_out;

    void *pY;
    void *pX16, *pC16, *pQ16, *pK16, *pV16, *pCX16, *pH16;
    void *pWq, *pWk, *pWv, *pWt, *pWc;
    cudaGetSymbolAddress(&pY, g_Y);
    cudaGetSymbolAddress(&pX16, g_X16);   cudaGetSymbolAddress(&pC16, g_C16);
    cudaGetSymbolAddress(&pQ16, g_Q16);
    cudaGetSymbolAddress(&pK16, g_K16);   cudaGetSymbolAddress(&pV16, g_V16);
    cudaGetSymbolAddress(&pCX16, g_CX16); cudaGetSymbolAddress(&pH16, g_H16);
    cudaGetSymbolAddress(&pWq, g_Wq16);   cudaGetSymbolAddress(&pWk, g_Wk16);
    cudaGetSymbolAddress(&pWv, g_Wv16);   cudaGetSymbolAddress(&pWt, g_Wt16);
    cudaGetSymbolAddress(&pWc, g_Wc16);

    cudaFuncSetAttribute(gemm_f16,
                         cudaFuncAttributeMaxDynamicSharedMemorySize,
                         GEMM_SMEM_TOTAL);
    cudaFuncSetAttribute(gemm_qkv,
                         cudaFuncAttributeMaxDynamicSharedMemorySize,
                         GEMM_SMEM_TOTAL);

    // 0-1: mask dtype detect + convert
    mask_detect_kernel<<<64, 256>>>(Mask);
    mask_convert_kernel<<<64, 256>>>(Mask);
    // 2: all fp32->fp16 conversions in one launch
    convert_all_kernel<<<8192, 256>>>(Cand, X, Wq, Wk, Wv, Wt, Wc,
                                      (f16*)pC16, (f16*)pX16,
                                      (f16*)pWq, (f16*)pWk, (f16*)pWv,
                                      (f16*)pWt, (f16*)pWc);
    // 3: fused Q/K/V GEMM (fp16 out)
    {
        dim3 g(HID / 128, CAND_M / 128, 3);
        gemm_qkv<<<g, 512, GEMM_SMEM_TOTAL>>>(
            (const f16*)pC16, (const f16*)pX16,
            (const f16*)pWk, (const f16*)pWv, (const f16*)pWq,
            bk, bv, bq,
            (f16*)pK16, (f16*)pV16, (f16*)pQ16);
    }
    // 4: attention -> CTX (all fp16)
    attn_kernel<<<(T_TOK * NH) / 8, 256>>>((const f16*)pQ16, (const f16*)pK16,
                                           (const f16*)pV16, (f16*)pCX16);
    // 5: H = gelu(CTX @ Wt^T + bt)  (fp16 out)  [ncu -s 5 target]
    {
        dim3 g(FF / 128, T_TOK / 128);
        gemm_f16<<<g, 512, GEMM_SMEM_TOTAL>>>(
            (const f16*)pCX16, (const f16*)pWt, bt,
            nullptr, (f16*)pH16, T_TOK, FF, HID, 1);
    }
    // 6: Y = H @ Wc^T + bc  (fp32 out)
    {
        dim3 g(HID / 128, T_TOK / 128);
        gemm_f16<<<g, 512, GEMM_SMEM_TOTAL>>>(
            (const f16*)pH16, (const f16*)pWc, bc,
            (float*)pY, nullptr, T_TOK, HID, FF, 0);
    }
    // 7: out = LayerNorm(Y + X)
    ln_kernel<<<T_TOK, 256>>>((const float*)pY, X, gam, bet, out);
}

// round 17
// speedup vs baseline: 2.5233x; 1.0047x over previous
#include <cuda_runtime.h>
#include <cuda_fp16.h>
#include <cstdint>

// ----------------------------------------------------------------------------
// Problem constants: B=4, S=2048 -> T=8192 tokens, HID=768, NH=12, HD=64,
// NC=8 candidates, FF=3072
// ----------------------------------------------------------------------------
#define T_TOK   8192
#define HID     768
#define NH      12
#define HD      64
#define NC      8
#define FF      3072
#define CAND_M  (T_TOK * NC)   // 65536
#define MASK_N  (T_TOK * NC)   // 65536

typedef __half  f16;
typedef __half2 f162;

// ----------------------------------------------------------------------------
// Scratch (device globals -- no allocation allowed anywhere)
// ----------------------------------------------------------------------------
__device__ float g_Y  [(size_t)T_TOK  * HID];
__device__ unsigned char g_mask[MASK_N];
__device__ int g_mflags[2];   // 0->1 transitions driven only by fixed input
                              // bytes -> idempotent across graph replays.

__device__ f16 g_X16 [(size_t)T_TOK  * HID];
__device__ f16 g_C16 [(size_t)CAND_M * HID];
__device__ f16 g_Q16 [(size_t)T_TOK  * HID];
__device__ f16 g_K16 [(size_t)CAND_M * HID];
__device__ f16 g_V16 [(size_t)CAND_M * HID];
__device__ f16 g_CX16[(size_t)T_TOK * HID];
__device__ f16 g_H16 [(size_t)T_TOK * FF];
__device__ f16 g_Wq16[(size_t)HID * HID];
__device__ f16 g_Wk16[(size_t)HID * HID];
__device__ f16 g_Wv16[(size_t)HID * HID];
__device__ f16 g_Wt16[(size_t)FF * HID];
__device__ f16 g_Wc16[(size_t)HID * FF];

// ----------------------------------------------------------------------------
// Helpers
// ----------------------------------------------------------------------------
__device__ __forceinline__ uint32_t smem_to_u32(const void* p) {
    uint32_t a;
    asm("{ .reg .u64 t; cvta.to.shared.u64 t, %1; cvt.u32.u64 %0, t; }"
        : "=r"(a) : "l"(p));
    return a;
}

#define CP_ASYNC16(dst_u32, src_ptr) \
    asm volatile("cp.async.cg.shared.global [%0], [%1], 16;" \
                 :: "r"(dst_u32), "l"(src_ptr) : "memory")
#define CP_COMMIT()  asm volatile("cp.async.commit_group;" ::: "memory")
#define CP_WAIT2()   asm volatile("cp.async.wait_group 2;" ::: "memory")

#define LDSM_X4(r0, r1, r2, r3, addr) \
    asm volatile("ldmatrix.sync.aligned.m8n8.x4.shared.b16 {%0,%1,%2,%3}, [%4];" \
                 : "=r"(r0), "=r"(r1), "=r"(r2), "=r"(r3) : "r"(addr))

__device__ __forceinline__ void mma16816(float* c, const uint32_t* a, const uint32_t* b)
{
    asm volatile(
        "mma.sync.aligned.m16n8k16.row.col.f32.f16.f16.f32 "
        "{%0,%1,%2,%3}, {%4,%5,%6,%7}, {%8,%9}, {%0,%1,%2,%3};"
        : "+f"(c[0]), "+f"(c[1]), "+f"(c[2]), "+f"(c[3])
        : "r"(a[0]), "r"(a[1]), "r"(a[2]), "r"(a[3]), "r"(b[0]), "r"(b[1]));
}

__device__ __forceinline__ float gelu_f(float x)
{
    return 0.5f * x * (1.0f + erff(x * 0.70710678118654752440f));
}

// ----------------------------------------------------------------------------
// GEMM (Round 16): ncu showed L1=67.8% / tensor=51% -> smem-traffic bound.
// Warp tile enlarged 32x32 -> 64x32: LDSM bytes per MMA drop 256 -> 192
// (A reused across 4 ni, B across 4 mi). CTA tile stays 128x128 with 8 warps
// (256 threads, 2x4 warp grid). __launch_bounds__(256,2) pins 2 CTAs/SM
// (regs<=128; smem 2x80KB < 228KB) -> 16 warps/SM.
// 4-stage cp.async, ldmatrix.x4 (verified mapping), SKP=40 conflict-free.
// ----------------------------------------------------------------------------
#define SKP         40
#define MAT_BYTES   (128 * SKP * 2)         // 10240 B
#define STAGE_BYTES (2 * MAT_BYTES)         // 20480 B
#define NSTAGE      4
#define GEMM_SMEM_TOTAL (NSTAGE * STAGE_BYTES)   // 81920 B

__device__ __forceinline__ void gemm_body(
    char* sm, const f16* __restrict__ A, const f16* __restrict__ B,
    const float* __restrict__ bias,
    float* __restrict__ outF, f16* __restrict__ outH,
    int N, int K, int bm, int bn, int gelu_flag)
{
    const uint32_t smem_u32 = smem_to_u32(sm);
    const int tid  = threadIdx.x;
    const int wid  = tid >> 5;          // 0..7
    const int lane = tid & 31;
    const int wm = (wid >> 2) * 64;     // warp M offset: 0/64
    const int wn = (wid & 3) * 32;      // warp N offset: 0/32/64/96

    // ldmatrix lane-relative byte offsets (verified mapping, Round 9):
    const int aRow = (lane & 7) + ((lane >> 3) & 1) * 8;
    const int aCol = (lane >> 4) * 8;
    uint32_t relA[4];
#pragma unroll
    for (int r = 0; r < 4; r++)
        relA[r] = (uint32_t)((wm + r * 16 + aRow) * SKP * 2 + aCol * 2);
    const int bRow = (lane & 7) + (lane >> 4) * 8;
    const int bCol = ((lane >> 3) & 1) * 8;
    const uint32_t relB0 = (uint32_t)((wn +  0 + bRow) * SKP * 2 + bCol * 2);
    const uint32_t relB1 = (uint32_t)((wn + 16 + bRow) * SKP * 2 + bCol * 2);

    float acc[4][4][4];
#pragma unroll
    for (int i = 0; i < 4; i++)
#pragma unroll
        for (int j = 0; j < 4; j++)
#pragma unroll
            for (int r = 0; r < 4; r++) acc[i][j][r] = 0.0f;

    // loader: 512 16B segments per matrix per chunk, 256 threads -> 2 each
    auto prefetch = [&](int k0, int s) {
        const uint32_t sb = smem_u32 + s * STAGE_BYTES;
#pragma unroll
        for (int h = 0; h < 2; h++) {
            const int id   = tid + h * 256;     // 0..511
            const int row  = id >> 2;           // 0..127
            const int lseg = id & 3;            // 16B seg within 64B row
            const uint32_t so = (uint32_t)(row * (SKP * 2) + lseg * 16);
            const size_t ga = (size_t)(bm + row) * K + k0 + lseg * 8;
            const size_t gb = (size_t)(bn + row) * K + k0 + lseg * 8;
            CP_ASYNC16(sb + so, A + ga);
            CP_ASYNC16(sb + MAT_BYTES + so, B + gb);
        }
    };

    const int nchunks = K >> 5;

#pragma unroll
    for (int p = 0; p < NSTAGE - 1; p++) {
        if (p < nchunks) prefetch(p << 5, p);
        CP_COMMIT();
    }

    for (int c = 0; c < nchunks; c++) {
        CP_WAIT2();
        __syncthreads();
        if (c + NSTAGE - 1 < nchunks)
            prefetch((c + NSTAGE - 1) << 5, (c + NSTAGE - 1) & (NSTAGE - 1));
        CP_COMMIT();

        const uint32_t st = smem_u32 + (c & (NSTAGE - 1)) * STAGE_BYTES;

#pragma unroll
        for (int kk = 0; kk < 32; kk += 16) {
            const uint32_t kb = st + kk * 2;
            uint32_t af[16], bf[8];

            LDSM_X4(af[0],  af[1],  af[2],  af[3],  kb + relA[0]);
            LDSM_X4(af[4],  af[5],  af[6],  af[7],  kb + relA[1]);
            LDSM_X4(af[8],  af[9],  af[10], af[11], kb + relA[2]);
            LDSM_X4(af[12], af[13], af[14], af[15], kb + relA[3]);
            LDSM_X4(bf[0], bf[1], bf[2], bf[3], kb + MAT_BYTES + relB0);
            LDSM_X4(bf[4], bf[5], bf[6], bf[7], kb + MAT_BYTES + relB1);

#pragma unroll
            for (int mi = 0; mi < 4; mi++)
#pragma unroll
                for (int ni = 0; ni < 4; ni++)
                    mma16816(acc[mi][ni], &af[mi * 4], &bf[ni * 2]);
        }
    }

    // epilogue
#pragma unroll
    for (int mi = 0; mi < 4; mi++) {
        const int r0 = bm + wm + mi * 16 + (lane >> 2);
#pragma unroll
        for (int ni = 0; ni < 4; ni++) {
            const int c0 = bn + wn + ni * 8 + (lane & 3) * 2;
            const float b0 = bias[c0], b1 = bias[c0 + 1];
            float v0 = acc[mi][ni][0] + b0;
            float v1 = acc[mi][ni][1] + b1;
            float v2 = acc[mi][ni][2] + b0;
            float v3 = acc[mi][ni][3] + b1;
            if (gelu_flag) {
                v0 = gelu_f(v0); v1 = gelu_f(v1);
                v2 = gelu_f(v2); v3 = gelu_f(v3);
            }
            if (outF) {
                *(float2*)(outF + (size_t)r0 * N + c0)       = make_float2(v0, v1);
                *(float2*)(outF + (size_t)(r0 + 8) * N + c0) = make_float2(v2, v3);
            } else {
                f162 p0; p0.x = __float2half(v0); p0.y = __float2half(v1);
                f162 p1; p1.x = __float2half(v2); p1.y = __float2half(v3);
                *(f162*)(outH + (size_t)r0 * N + c0)       = p0;
                *(f162*)(outH + (size_t)(r0 + 8) * N + c0) = p1;
            }
        }
    }
}

// Generic GEMM (H and Y stages)
__global__ void __launch_bounds__(256, 2)
gemm_f16(const f16* __restrict__ A, const f16* __restrict__ B,
         const float* __restrict__ bias,
         float* __restrict__ outF, f16* __restrict__ outH,
         int M, int N, int K, int gelu_flag)
{
    extern __shared__ __align__(16) char sm[];
    gemm_body(sm, A, B, bias, outF, outH, N, K,
              blockIdx.y * 128, blockIdx.x * 128, gelu_flag);
}

// Fused Q/K/V GEMM: blockIdx.z selects the problem. z=0: K, z=1: V (M=65536),
// z=2: Q (M=8192; y>=64 exits). All share N=K=768, fp16 out, no gelu.
__global__ void __launch_bounds__(256, 2)
gemm_qkv(const f16* __restrict__ C16, const f16* __restrict__ X16,
         const f16* __restrict__ Wk, const f16* __restrict__ Wv,
         const f16* __restrict__ Wq,
         const float* __restrict__ bk, const float* __restrict__ bv,
         const float* __restrict__ bq,
         f16* __restrict__ K16, f16* __restrict__ V16, f16* __restrict__ Q16)
{
    extern __shared__ __align__(16) char sm[];
    const int z = blockIdx.z;
    if (z == 2 && blockIdx.y >= (T_TOK / 128)) return;
    const f16* A = (z == 2) ? X16 : C16;
    const f16* B = (z == 0) ? Wk : (z == 1) ? Wv : Wq;
    const float* bias = (z == 0) ? bk : (z == 1) ? bv : bq;
    f16* out = (z == 0) ? K16 : (z == 1) ? V16 : Q16;
    gemm_body(sm, A, B, bias, nullptr, out, HID, HID,
              blockIdx.y * 128, blockIdx.x * 128, 0);
}

// ----------------------------------------------------------------------------
// Mega-convert: all fp32->fp16 conversions in ONE grid-strided kernel.
// ----------------------------------------------------------------------------
#define SEG_C   (CAND_M * HID / 4)
#define SEG_X   (T_TOK * HID / 4)
#define SEG_W   (HID * HID / 4)
#define SEG_T   (FF * HID / 4)
#define CUM0    SEG_C
#define CUM1    (CUM0 + SEG_X)
#define CUM2    (CUM1 + SEG_W)
#define CUM3    (CUM2 + SEG_W)
#define CUM4    (CUM3 + SEG_W)
#define CUM5    (CUM4 + SEG_T)
#define CUM6    (CUM5 + SEG_T)

__global__ __launch_bounds__(256)
void convert_all_kernel(const float* __restrict__ Cand, const float* __restrict__ X,
                        const float* __restrict__ Wq, const float* __restrict__ Wk,
                        const float* __restrict__ Wv, const float* __restrict__ Wt,
                        const float* __restrict__ Wc,
                        f16* __restrict__ C16, f16* __restrict__ X16,
                        f16* __restrict__ Wq16, f16* __restrict__ Wk16,
                        f16* __restrict__ Wv16, f16* __restrict__ Wt16,
                        f16* __restrict__ Wc16)
{
    for (int i = blockIdx.x * 256 + threadIdx.x; i < CUM6; i += gridDim.x * 256) {
        const float* src;
        f16* dst;
        int off;
        if      (i < CUM0) { src = Cand; dst = C16;  off = i; }
        else if (i < CUM1) { src = X;    dst = X16;  off = i - CUM0; }
        else if (i < CUM2) { src = Wq;   dst = Wq16; off = i - CUM1; }
        else if (i < CUM3) { src = Wk;   dst = Wk16; off = i - CUM2; }
        else if (i < CUM4) { src = Wv;   dst = Wv16; off = i - CUM3; }
        else if (i < CUM5) { src = Wt;   dst = Wt16; off = i - CUM4; }
        else               { src = Wc;   dst = Wc16; off = i - CUM5; }
        const float4 v = *(const float4*)(src + (size_t)off * 4);
        f162 p0; p0.x = __float2half(v.x); p0.y = __float2half(v.y);
        f162 p1; p1.x = __float2half(v.z); p1.y = __float2half(v.w);
        uint2 pv;
        pv.x = *(const uint32_t*)&p0; pv.y = *(const uint32_t*)&p1;
        *(uint2*)(dst + (size_t)off * 4) = pv;
    }
}

// ----------------------------------------------------------------------------
// Mask dtype detect + convert (parallel, idempotent flags)
// ----------------------------------------------------------------------------
__global__ __launch_bounds__(256)
void mask_detect_kernel(const void* __restrict__ mp)
{
    const unsigned char* b = (const unsigned char*)mp;
    int local_nonbin = 0, local_offnz = 0;
    for (int i = blockIdx.x * 256 + threadIdx.x; i < MASK_N; i += gridDim.x * 256) {
        unsigned char v = b[i];
        if (v > 1)                  local_nonbin = 1;
        if ((i & 3) != 0 && v != 0) local_offnz = 1;
    }
    if (local_nonbin) atomicOr(&g_mflags[0], 1);
    if (local_offnz)  atomicOr(&g_mflags[1], 1);
}

__global__ __launch_bounds__(256)
void mask_convert_kernel(const void* __restrict__ mp)
{
    const int nonbin = g_mflags[0], offnz = g_mflags[1];
    const int i0 = blockIdx.x * 256 + threadIdx.x;
    const int stride = gridDim.x * 256;
    if (nonbin) {
        const float* f = (const float*)mp;
        for (int i = i0; i < MASK_N; i += stride)
            g_mask[i] = (f[i] != 0.0f) ? 1 : 0;
    } else if (offnz) {
        const unsigned char* b = (const unsigned char*)mp;
        for (int i = i0; i < MASK_N; i += stride)
            g_mask[i] = (b[i] != 0) ? 1 : 0;
    } else {
        const int* ip = (const int*)mp;
        for (int i = i0; i < MASK_N; i += stride)
            g_mask[i] = (ip[i] != 0) ? 1 : 0;
    }
}

// ----------------------------------------------------------------------------
// Attention: one warp per (token, head). Q, K, V all fp16; CTX fp16 out.
// ----------------------------------------------------------------------------
__global__ __launch_bounds__(256)
void attn_kernel(const f16* __restrict__ Qb, const f16* __restrict__ Kb,
                 const f16* __restrict__ Vb, f16* __restrict__ CX)
{
    const int w    = (blockIdx.x * blockDim.x + threadIdx.x) >> 5;
    const int lane = threadIdx.x & 31;
    if (w >= T_TOK * NH) return;
    const int t = w / NH;
    const int h = w % NH;

    const size_t qoff = (size_t)t * HID + h * HD + lane * 2;
    const f162 qh = *(const f162*)(Qb + qoff);
    const float qx = __half2float(qh.x), qy = __half2float(qh.y);

    float s[NC];
    unsigned allm = 1;
#pragma unroll
    for (int n = 0; n < NC; n++) {
        const f162 kv = *(const f162*)(Kb + ((size_t)t * NC + n) * HID + h * HD + lane * 2);
        float p = qx * __half2float(kv.x) + qy * __half2float(kv.y);
#pragma unroll
        for (int o = 16; o > 0; o >>= 1)
            p += __shfl_xor_sync(0xffffffffu, p, o);
        const unsigned char mn = g_mask[t * NC + n];
        allm &= (mn != 0);
        s[n] = mn ? 1e-10f : p * 0.125f;
    }

    float mx = s[0];
#pragma unroll
    for (int n = 1; n < NC; n++) mx = fmaxf(mx, s[n]);
    float sum = 0.0f;
#pragma unroll
    for (int n = 0; n < NC; n++) { s[n] = expf(s[n] - mx); sum += s[n]; }
    const float inv = 1.0f / sum;

    float2 c = make_float2(0.0f, 0.0f);
#pragma unroll
    for (int n = 0; n < NC; n++) {
        const f162 vv = *(const f162*)(Vb + ((size_t)t * NC + n) * HID + h * HD + lane * 2);
        const float p = s[n] * inv;
        c.x += p * __half2float(vv.x);
        c.y += p * __half2float(vv.y);
    }
    if (allm) { c.x = 0.0f; c.y = 0.0f; }

    f162 hp; hp.x = __float2half(c.x); hp.y = __float2half(c.y);
    *(f162*)(CX + qoff) = hp;
}

// ----------------------------------------------------------------------------
// Residual + LayerNorm
// ----------------------------------------------------------------------------
__global__ __launch_bounds__(256)
void ln_kernel(const float* __restrict__ Y, const float* __restrict__ X,
               const float* __restrict__ gamma, const float* __restrict__ beta,
               float* __restrict__ O)
{
    const int t   = blockIdx.x;
    const int tid = threadIdx.x;
    const float* yp = Y + (size_t)t * HID;
    const float* xp = X + (size_t)t * HID;

    float v[3];
    float sum = 0.0f, sq = 0.0f;
#pragma unroll
    for (int i = 0; i < 3; i++) {
        const int idx = tid + i * 256;
        v[i] = yp[idx] + xp[idx];
        sum += v[i];
        sq  += v[i] * v[i];
    }

    const int lane = tid & 31, wid = tid >> 5;
#pragma unroll
    for (int o = 16; o > 0; o >>= 1) {
        sum += __shfl_xor_sync(0xffffffffu, sum, o);
        sq  += __shfl_xor_sync(0xffffffffu, sq,  o);
    }
    __shared__ float rs[8], rq[8];
    if (lane == 0) { rs[wid] = sum; rq[wid] = sq; }
    __syncthreads();
    sum = 0.0f; sq = 0.0f;
#pragma unroll
    for (int i = 0; i < 8; i++) { sum += rs[i]; sq += rq[i]; }

    const float mean = sum * (1.0f / HID);
    const float var  = sq * (1.0f / HID) - mean * mean;
    const float inv  = rsqrtf(var + 1e-12f);

    float* op = O + (size_t)t * HID;
#pragma unroll
    for (int i = 0; i < 3; i++) {
        const int idx = tid + i * 256;
        op[idx] = (v[i] - mean) * inv * gamma[idx] + beta[idx];
    }
}

// ----------------------------------------------------------------------------
// kernel_launch — 8 launches
//   0 mask_detect, 1 mask_convert, 2 convert_all, 3 gemm_qkv,
//   4 attn, 5 H GEMM (ncu -s 5 target), 6 Y GEMM, 7 LN
// ----------------------------------------------------------------------------
extern "C" void kernel_launch(void* const* d_in, const int* in_sizes, int n_in,
                              void* d_out, int out_size)
{
    const float* X    = (const float*)d_in[0];
    const float* Cand = (const float*)d_in[1];
    const void*  Mask = d_in[2];
    const float* Wq   = (const float*)d_in[3];
    const float* bq   = (const float*)d_in[4];
    const float* Wk   = (const float*)d_in[5];
    const float* bk   = (const float*)d_in[6];
    const float* Wv   = (const float*)d_in[7];
    const float* bv   = (const float*)d_in[8];
    const float* Wt   = (const float*)d_in[9];
    const float* bt   = (const float*)d_in[10];
    const float* Wc   = (const float*)d_in[11];
    const float* bc   = (const float*)d_in[12];
    const float* gam  = (const float*)d_in[13];
    const float* bet  = (const float*)d_in[14];
    float* out = (float*)d_out;

    void *pY;
    void *pX16, *pC16, *pQ16, *pK16, *pV16, *pCX16, *pH16;
    void *pWq, *pWk, *pWv, *pWt, *pWc;
    cudaGetSymbolAddress(&pY, g_Y);
    cudaGetSymbolAddress(&pX16, g_X16);   cudaGetSymbolAddress(&pC16, g_C16);
    cudaGetSymbolAddress(&pQ16, g_Q16);
    cudaGetSymbolAddress(&pK16, g_K16);   cudaGetSymbolAddress(&pV16, g_V16);
    cudaGetSymbolAddress(&pCX16, g_CX16); cudaGetSymbolAddress(&pH16, g_H16);
    cudaGetSymbolAddress(&pWq, g_Wq16);   cudaGetSymbolAddress(&pWk, g_Wk16);
    cudaGetSymbolAddress(&pWv, g_Wv16);   cudaGetSymbolAddress(&pWt, g_Wt16);
    cudaGetSymbolAddress(&pWc, g_Wc16);

    cudaFuncSetAttribute(gemm_f16,
                         cudaFuncAttributeMaxDynamicSharedMemorySize,
                         GEMM_SMEM_TOTAL);
    cudaFuncSetAttribute(gemm_qkv,
                         cudaFuncAttributeMaxDynamicSharedMemorySize,
                         GEMM_SMEM_TOTAL);

    // 0-1: mask dtype detect + convert
    mask_detect_kernel<<<64, 256>>>(Mask);
    mask_convert_kernel<<<64, 256>>>(Mask);
    // 2: all fp32->fp16 conversions in one launch
    convert_all_kernel<<<8192, 256>>>(Cand, X, Wq, Wk, Wv, Wt, Wc,
                                      (f16*)pC16, (f16*)pX16,
                                      (f16*)pWq, (f16*)pWk, (f16*)pWv,
                                      (f16*)pWt, (f16*)pWc);
    // 3: fused Q/K/V GEMM (fp16 out)
    {
        dim3 g(HID / 128, CAND_M / 128, 3);
        gemm_qkv<<<g, 256, GEMM_SMEM_TOTAL>>>(
            (const f16*)pC16, (const f16*)pX16,
            (const f16*)pWk, (const f16*)pWv, (const f16*)pWq,
            bk, bv, bq,
            (f16*)pK16, (f16*)pV16, (f16*)pQ16);
    }
    // 4: attention -> CTX (all fp16)
    attn_kernel<<<(T_TOK * NH) / 8, 256>>>((const f16*)pQ16, (const f16*)pK16,
                                           (const f16*)pV16, (f16*)pCX16);
    // 5: H = gelu(CTX @ Wt^T + bt)  (fp16 out)  [ncu -s 5 target]
    {
        dim3 g(FF / 128, T_TOK / 128);
        gemm_f16<<<g, 256, GEMM_SMEM_TOTAL>>>(
            (const f16*)pCX16, (const f16*)pWt, bt,
            nullptr, (f16*)pH16, T_TOK, FF, HID, 1);
    }
    // 6: Y = H @ Wc^T + bc  (fp32 out)
    {
        dim3 g(HID / 128, T_TOK / 128);
        gemm_f16<<<g, 256, GEMM_SMEM_TOTAL>>>(
            (const f16*)pH16, (const f16*)pWc, bc,
            (float*)pY, nullptr, T_TOK, HID, FF, 0);
    }
    // 7: out = LayerNorm(Y + X)
    ln_kernel<<<T_TOK, 256>>>((const float*)pY, X, gam, bet, out);
}